// round 4
// baseline (speedup 1.0000x reference)
#include <cuda_runtime.h>
#include <math.h>
#include <float.h>

#define KB 10
#define TT 70
#define SS 128
#define EE 1024
#define HH 1024
#define VV 32000
#define PAD_ 0
#define START_ 1
#define EOS_ 2
#define NEGF (-1000000000.0f)
#define NLOG_BLK 250   // logits blocks, 128 vocab rows each

// ---------------- device scratch ----------------
__device__ __align__(16) float d_keys[SS * HH];     // keys[s][h]
__device__ __align__(16) float d_Pt[HH * SS];       // Pt[j][s]
__device__ __align__(16) float d_h[KB * HH], d_c[KB * HH];
__device__ __align__(16) float d_xy[KB * 2048];     // [emb | prevOut] per beam
__device__ __align__(16) float d_hn[KB * HH], d_cn[KB * HH], d_on[KB * HH];
__device__ __align__(16) float d_alpha[KB * SS];
__device__ __align__(16) float d_gates[KB * 4 * HH];   // [k][row]
__device__ float d_scores[KB];
__device__ int d_fin[KB];
__device__ int d_tok[2][KB * (TT + 1)];
__device__ float d_pmax[NLOG_BLK * KB], d_psum[NLOG_BLK * KB];
__device__ float d_ptv[NLOG_BLK * KB * 10];
__device__ int   d_pti[NLOG_BLK * KB * 10];

__device__ __forceinline__ float sigm(float x) { return 1.f / (1.f + expf(-x)); }
__device__ __forceinline__ float dot4(float4 a, float4 b) {
    return a.x * b.x + a.y * b.y + a.z * b.z + a.w * b.w;
}

// ---------------- init ----------------
__global__ void k_init(const float* __restrict__ h0, const float* __restrict__ c0,
                       const float* __restrict__ emb) {
    int tid = blockIdx.x * blockDim.x + threadIdx.x;
    int nt = gridDim.x * blockDim.x;
    for (int i = tid; i < KB * HH; i += nt) {
        int h = i & 1023;
        d_h[i] = h0[h];
        d_c[i] = c0[h];
    }
    for (int i = tid; i < KB * 2048; i += nt) {
        int p = i & 2047;
        d_xy[i] = (p < 1024) ? emb[(size_t)START_ * EE + p] : 0.f;
    }
    for (int i = tid; i < KB * (TT + 1); i += nt)
        d_tok[0][i] = (i % (TT + 1) == 0) ? START_ : PAD_;
    if (tid < KB) { d_scores[tid] = (tid == 0) ? 0.f : NEGF; d_fin[tid] = 0; }
}

// ---------------- precompute keys / Pt ----------------
__global__ void k_prep(const float* __restrict__ enc, const float* __restrict__ W,
                       int ldw, int mode) {
    __shared__ float smW[16][129];
    __shared__ float smE[16][129];
    int j0 = blockIdx.x * 16, s0 = blockIdx.y * 16;
    int tid = threadIdx.x;
    int jj = tid & 15, ssn = tid >> 4;
    float acc = 0.f;
    for (int vc = 0; vc < 2 * EE; vc += 128) {
        for (int l = tid; l < 16 * 128; l += 256) {
            int r = l >> 7, cc = l & 127;
            smW[r][cc] = W[(size_t)(j0 + r) * ldw + vc + cc];
            smE[r][cc] = enc[(size_t)(s0 + r) * (2 * EE) + vc + cc];
        }
        __syncthreads();
        #pragma unroll
        for (int x = 0; x < 128; x++) acc += smW[jj][x] * smE[ssn][x];
        __syncthreads();
    }
    int j = j0 + jj, s = s0 + ssn;
    if (mode == 0) d_keys[s * HH + j] = acc;
    else           d_Pt[j * SS + s] = acc;
}

// ------- gates GEMV, R=4 rows/warp, 2-chunk unroll (8 LDG.128 in flight) -----
__global__ void __launch_bounds__(256, 1) k_gates(
        const float* __restrict__ W_ih, const float* __restrict__ b_ih,
        const float* __restrict__ W_hh, const float* __restrict__ b_hh) {
    int wid = threadIdx.x >> 5, lane = threadIdx.x & 31;
    int grp = blockIdx.x * 8 + wid;    // 0..1023
    int r0 = grp * 4;
    float acc[4][KB];
    #pragma unroll
    for (int r = 0; r < 4; r++)
        #pragma unroll
        for (int k = 0; k < KB; k++) acc[r][k] = 0.f;

    const float4* w0 = (const float4*)(W_ih + (size_t)(r0 + 0) * 2048);
    const float4* w1 = (const float4*)(W_ih + (size_t)(r0 + 1) * 2048);
    const float4* w2 = (const float4*)(W_ih + (size_t)(r0 + 2) * 2048);
    const float4* w3 = (const float4*)(W_ih + (size_t)(r0 + 3) * 2048);
    #pragma unroll
    for (int ch = 0; ch < 16; ch += 2) {
        int i0 = ch * 32 + lane, i1 = i0 + 32;
        float4 a0 = w0[i0], a1 = w1[i0], a2 = w2[i0], a3 = w3[i0];
        float4 b0 = w0[i1], b1 = w1[i1], b2 = w2[i1], b3 = w3[i1];
        #pragma unroll
        for (int k = 0; k < KB; k++) {
            float4 yv = ((const float4*)(d_xy + k * 2048))[i0];
            acc[0][k] += dot4(a0, yv); acc[1][k] += dot4(a1, yv);
            acc[2][k] += dot4(a2, yv); acc[3][k] += dot4(a3, yv);
        }
        #pragma unroll
        for (int k = 0; k < KB; k++) {
            float4 yv = ((const float4*)(d_xy + k * 2048))[i1];
            acc[0][k] += dot4(b0, yv); acc[1][k] += dot4(b1, yv);
            acc[2][k] += dot4(b2, yv); acc[3][k] += dot4(b3, yv);
        }
    }
    const float4* u0 = (const float4*)(W_hh + (size_t)(r0 + 0) * 1024);
    const float4* u1 = (const float4*)(W_hh + (size_t)(r0 + 1) * 1024);
    const float4* u2 = (const float4*)(W_hh + (size_t)(r0 + 2) * 1024);
    const float4* u3 = (const float4*)(W_hh + (size_t)(r0 + 3) * 1024);
    #pragma unroll
    for (int ch = 0; ch < 8; ch += 2) {
        int i0 = ch * 32 + lane, i1 = i0 + 32;
        float4 a0 = u0[i0], a1 = u1[i0], a2 = u2[i0], a3 = u3[i0];
        float4 b0 = u0[i1], b1 = u1[i1], b2 = u2[i1], b3 = u3[i1];
        #pragma unroll
        for (int k = 0; k < KB; k++) {
            float4 yv = ((const float4*)(d_h + k * 1024))[i0];
            acc[0][k] += dot4(a0, yv); acc[1][k] += dot4(a1, yv);
            acc[2][k] += dot4(a2, yv); acc[3][k] += dot4(a3, yv);
        }
        #pragma unroll
        for (int k = 0; k < KB; k++) {
            float4 yv = ((const float4*)(d_h + k * 1024))[i1];
            acc[0][k] += dot4(b0, yv); acc[1][k] += dot4(b1, yv);
            acc[2][k] += dot4(b2, yv); acc[3][k] += dot4(b3, yv);
        }
    }
    float bs0 = b_ih[r0] + b_hh[r0];
    float bs1 = b_ih[r0 + 1] + b_hh[r0 + 1];
    float bs2 = b_ih[r0 + 2] + b_hh[r0 + 2];
    float bs3 = b_ih[r0 + 3] + b_hh[r0 + 3];
    #pragma unroll
    for (int r = 0; r < 4; r++) {
        float bs = (r == 0) ? bs0 : (r == 1) ? bs1 : (r == 2) ? bs2 : bs3;
        #pragma unroll
        for (int k = 0; k < KB; k++) {
            float v = acc[r][k];
            for (int o = 16; o; o >>= 1) v += __shfl_down_sync(0xffffffffu, v, o);
            if (lane == 0) d_gates[k * 4096 + r0 + r] = v + bs;
        }
    }
}

// ------------- LSTM cell + attention scores + softmax (block per beam) -------
__global__ void __launch_bounds__(1024) k_attn(const int* __restrict__ src_len) {
    int k = blockIdx.x;
    int tid = threadIdx.x;
    __shared__ float s_h[1024];
    __shared__ float s_e[128];
    __shared__ float s_m, s_t;

    int j = tid;
    float gi = d_gates[k * 4096 + j];
    float gf = d_gates[k * 4096 + 1024 + j];
    float gg = d_gates[k * 4096 + 2048 + j];
    float go = d_gates[k * 4096 + 3072 + j];
    float cp = d_c[k * 1024 + j];
    float cn = sigm(gf) * cp + sigm(gi) * tanhf(gg);
    float hn = sigm(go) * tanhf(cn);
    d_cn[k * 1024 + j] = cn;
    d_hn[k * 1024 + j] = hn;
    s_h[j] = hn;
    __syncthreads();

    int wid = tid >> 5, lane = tid & 31;
    int slen = src_len[0];
    #pragma unroll
    for (int si = 0; si < 4; si++) {
        int s = wid * 4 + si;
        const float4* kr = (const float4*)(d_keys + s * 1024);
        const float4* hh = (const float4*)s_h;
        float a = 0.f;
        #pragma unroll
        for (int it = 0; it < 8; it++) {
            float4 xv = kr[it * 32 + lane];
            float4 yv = hh[it * 32 + lane];
            a += dot4(xv, yv);
        }
        for (int o = 16; o; o >>= 1) a += __shfl_down_sync(0xffffffffu, a, o);
        if (lane == 0) s_e[s] = (s >= slen) ? NEGF : a;
    }
    __syncthreads();
    if (wid == 0) {
        float v0 = s_e[lane], v1 = s_e[lane + 32], v2 = s_e[lane + 64], v3 = s_e[lane + 96];
        float m = fmaxf(fmaxf(v0, v1), fmaxf(v2, v3));
        for (int o = 16; o; o >>= 1) m = fmaxf(m, __shfl_xor_sync(0xffffffffu, m, o));
        float t = expf(v0 - m) + expf(v1 - m) + expf(v2 - m) + expf(v3 - m);
        for (int o = 16; o; o >>= 1) t += __shfl_xor_sync(0xffffffffu, t, o);
        if (lane == 0) { s_m = m; s_t = t; }
    }
    __syncthreads();
    if (tid < 128) d_alpha[k * 128 + tid] = expf(s_e[tid] - s_m) / s_t;
}

// ---- out[k][j] = tanh(alpha·Pt[j] + Wcomb2[j]·h_new), R=4 rows/warp ---------
__global__ void __launch_bounds__(256) k_out(const float* __restrict__ W_comb) {
    int wid = threadIdx.x >> 5, lane = threadIdx.x & 31;
    int grp = blockIdx.x * 8 + wid;   // 0..255
    int r0 = grp * 4;
    float acc[4][KB];
    #pragma unroll
    for (int r = 0; r < 4; r++)
        #pragma unroll
        for (int k = 0; k < KB; k++) acc[r][k] = 0.f;
    {
        float4 p0 = ((const float4*)(d_Pt + (r0 + 0) * 128))[lane];
        float4 p1 = ((const float4*)(d_Pt + (r0 + 1) * 128))[lane];
        float4 p2 = ((const float4*)(d_Pt + (r0 + 2) * 128))[lane];
        float4 p3 = ((const float4*)(d_Pt + (r0 + 3) * 128))[lane];
        #pragma unroll
        for (int k = 0; k < KB; k++) {
            float4 av = ((const float4*)(d_alpha + k * 128))[lane];
            acc[0][k] += dot4(p0, av); acc[1][k] += dot4(p1, av);
            acc[2][k] += dot4(p2, av); acc[3][k] += dot4(p3, av);
        }
    }
    const float4* w0 = (const float4*)(W_comb + (size_t)(r0 + 0) * 3072 + 2048);
    const float4* w1 = (const float4*)(W_comb + (size_t)(r0 + 1) * 3072 + 2048);
    const float4* w2 = (const float4*)(W_comb + (size_t)(r0 + 2) * 3072 + 2048);
    const float4* w3 = (const float4*)(W_comb + (size_t)(r0 + 3) * 3072 + 2048);
    #pragma unroll
    for (int ch = 0; ch < 8; ch += 2) {
        int i0 = ch * 32 + lane, i1 = i0 + 32;
        float4 a0 = w0[i0], a1 = w1[i0], a2 = w2[i0], a3 = w3[i0];
        float4 b0 = w0[i1], b1 = w1[i1], b2 = w2[i1], b3 = w3[i1];
        #pragma unroll
        for (int k = 0; k < KB; k++) {
            float4 yv = ((const float4*)(d_hn + k * 1024))[i0];
            acc[0][k] += dot4(a0, yv); acc[1][k] += dot4(a1, yv);
            acc[2][k] += dot4(a2, yv); acc[3][k] += dot4(a3, yv);
        }
        #pragma unroll
        for (int k = 0; k < KB; k++) {
            float4 yv = ((const float4*)(d_hn + k * 1024))[i1];
            acc[0][k] += dot4(b0, yv); acc[1][k] += dot4(b1, yv);
            acc[2][k] += dot4(b2, yv); acc[3][k] += dot4(b3, yv);
        }
    }
    #pragma unroll
    for (int r = 0; r < 4; r++)
        #pragma unroll
        for (int k = 0; k < KB; k++) {
            float v = acc[r][k];
            for (int o = 16; o; o >>= 1) v += __shfl_down_sync(0xffffffffu, v, o);
            if (lane == 0) d_on[k * HH + r0 + r] = tanhf(v);
        }
}

// ----- vocab logits (R=4 rows/warp) fused with per-block top-10 + lse -------
__global__ void __launch_bounds__(256) k_logits(const float* __restrict__ Wv) {
    __shared__ float s_on[KB * 1024];   // 40KB
    __shared__ float s_lg[KB][128];     // 5KB
    int tid = threadIdx.x;
    int wid = tid >> 5, lane = tid & 31;
    {
        const float4* src = (const float4*)d_on;
        float4* dst = (float4*)s_on;
        for (int i = tid; i < KB * 256; i += 256) dst[i] = src[i];
    }
    __syncthreads();
    int base = blockIdx.x * 128;

    for (int gg = 0; gg < 4; gg++) {
        int jloc = wid * 16 + gg * 4;          // 0..127 local row
        int r = base + jloc;
        float acc[4][KB];
        #pragma unroll
        for (int rr = 0; rr < 4; rr++)
            #pragma unroll
            for (int k = 0; k < KB; k++) acc[rr][k] = 0.f;
        const float4* w0 = (const float4*)(Wv + (size_t)r * 1024);
        const float4* w1 = w0 + 256;
        const float4* w2 = w0 + 512;
        const float4* w3 = w0 + 768;
        #pragma unroll
        for (int ch = 0; ch < 8; ch += 2) {
            int i0 = ch * 32 + lane, i1 = i0 + 32;
            float4 a0 = w0[i0], a1 = w1[i0], a2 = w2[i0], a3 = w3[i0];
            float4 b0 = w0[i1], b1 = w1[i1], b2 = w2[i1], b3 = w3[i1];
            #pragma unroll
            for (int k = 0; k < KB; k++) {
                float4 yv = ((const float4*)(s_on + k * 1024))[i0];
                acc[0][k] += dot4(a0, yv); acc[1][k] += dot4(a1, yv);
                acc[2][k] += dot4(a2, yv); acc[3][k] += dot4(a3, yv);
            }
            #pragma unroll
            for (int k = 0; k < KB; k++) {
                float4 yv = ((const float4*)(s_on + k * 1024))[i1];
                acc[0][k] += dot4(b0, yv); acc[1][k] += dot4(b1, yv);
                acc[2][k] += dot4(b2, yv); acc[3][k] += dot4(b3, yv);
            }
        }
        #pragma unroll
        for (int rr = 0; rr < 4; rr++)
            #pragma unroll
            for (int k = 0; k < KB; k++) {
                float v = acc[rr][k];
                for (int o = 16; o; o >>= 1) v += __shfl_down_sync(0xffffffffu, v, o);
                if (lane == 0) s_lg[k][jloc + rr] = v;
            }
    }
    __syncthreads();

    // per-beam block reduction: max, sumexp, top-10 (warp per beam)
    for (int k = wid; k < KB; k += 8) {
        float4 vv = ((const float4*)s_lg[k])[lane];
        float v0 = vv.x, v1 = vv.y, v2 = vv.z, v3 = vv.w;
        int gbase = k * VV + base + lane * 4;
        int i0 = gbase, i1 = gbase + 1, i2 = gbase + 2, i3 = gbase + 3;
        #define CSWAP(va, ia, vb, ib) { if (vb > va) { float tv = va; va = vb; vb = tv; int ti = ia; ia = ib; ib = ti; } }
        CSWAP(v0, i0, v1, i1); CSWAP(v2, i2, v3, i3);
        CSWAP(v0, i0, v2, i2); CSWAP(v1, i1, v3, i3);
        CSWAP(v1, i1, v2, i2);
        #undef CSWAP
        float m = v0;
        for (int o = 16; o; o >>= 1) m = fmaxf(m, __shfl_xor_sync(0xffffffffu, m, o));
        float ssum = expf(v0 - m) + expf(v1 - m) + expf(v2 - m) + expf(v3 - m);
        for (int o = 16; o; o >>= 1) ssum += __shfl_xor_sync(0xffffffffu, ssum, o);
        if (lane == 0) {
            d_pmax[blockIdx.x * KB + k] = m;
            d_psum[blockIdx.x * KB + k] = ssum;
        }
        int head = 0;
        for (int r2 = 0; r2 < 10; r2++) {
            float cv; int ci;
            if      (head == 0) { cv = v0; ci = i0; }
            else if (head == 1) { cv = v1; ci = i1; }
            else if (head == 2) { cv = v2; ci = i2; }
            else if (head == 3) { cv = v3; ci = i3; }
            else { cv = -FLT_MAX; ci = 0x7fffffff; }
            float bv = cv; int bi = ci; int bl = lane;
            for (int o = 16; o; o >>= 1) {
                float ov = __shfl_down_sync(0xffffffffu, bv, o);
                int oi = __shfl_down_sync(0xffffffffu, bi, o);
                int ol = __shfl_down_sync(0xffffffffu, bl, o);
                if (ov > bv || (ov == bv && oi < bi)) { bv = ov; bi = oi; bl = ol; }
            }
            bv = __shfl_sync(0xffffffffu, bv, 0);
            bi = __shfl_sync(0xffffffffu, bi, 0);
            bl = __shfl_sync(0xffffffffu, bl, 0);
            if (lane == bl) head++;
            if (lane == 0) {
                d_ptv[(blockIdx.x * KB + k) * 10 + r2] = bv;
                d_pti[(blockIdx.x * KB + k) * 10 + r2] = bi;
            }
        }
    }
}

// ------- merge partials: exact lse, global top-10, token update, gather ------
__global__ void __launch_bounds__(1024) k_merge(int t, int cur,
                                                const float* __restrict__ emb) {
    int tid = threadIdx.x;
    int wid = tid >> 5, lane = tid & 31;
    __shared__ float s_mx[KB], s_ls[KB], s_sc[KB];
    __shared__ int s_fin[KB];
    __shared__ float s_wv[320];
    __shared__ int s_wi[320];
    __shared__ float s_tv[KB];
    __shared__ int s_ti[KB];
    __shared__ int s_row[KB], s_col[KB];
    if (tid < KB) { s_sc[tid] = d_scores[tid]; s_fin[tid] = d_fin[tid]; }
    __syncthreads();

    if (wid < KB) {
        int k = wid;
        float m = -FLT_MAX;
        for (int b = lane; b < NLOG_BLK; b += 32) m = fmaxf(m, d_pmax[b * KB + k]);
        for (int o = 16; o; o >>= 1) m = fmaxf(m, __shfl_xor_sync(0xffffffffu, m, o));
        float s = 0.f;
        for (int b = lane; b < NLOG_BLK; b += 32)
            s += d_psum[b * KB + k] * expf(d_pmax[b * KB + k] - m);
        for (int o = 16; o; o >>= 1) s += __shfl_xor_sync(0xffffffffu, s, o);
        if (lane == 0) { s_mx[k] = m; s_ls[k] = logf(s); }
    }
    __syncthreads();

    float lv[10]; int li[10];
    #pragma unroll
    for (int p = 0; p < 10; p++) { lv[p] = -FLT_MAX; li[p] = 0x7fffffff; }

    const int NE = NLOG_BLK * KB * 10;
    for (int e = tid; e < NE; e += 1024) {
        int k = (e / 10) % KB;
        if (s_fin[k]) continue;
        float val = s_sc[k] + d_ptv[e] - s_mx[k] - s_ls[k];
        int idx = d_pti[e];
        if (val > lv[9] || (val == lv[9] && idx < li[9])) {
            int cnt = 0;
            #pragma unroll
            for (int p = 0; p < 10; p++)
                cnt += (lv[p] > val) || (lv[p] == val && li[p] < idx);
            #pragma unroll
            for (int p = 9; p >= 1; p--)
                if (p > cnt) { lv[p] = lv[p - 1]; li[p] = li[p - 1]; }
            #pragma unroll
            for (int p = 0; p < 10; p++)
                if (p == cnt) { lv[p] = val; li[p] = idx; }
        }
    }
    if (tid < KB && s_fin[tid]) {
        float val = s_sc[tid];
        int idx = tid * VV + PAD_;
        if (val > lv[9] || (val == lv[9] && idx < li[9])) {
            int cnt = 0;
            #pragma unroll
            for (int p = 0; p < 10; p++)
                cnt += (lv[p] > val) || (lv[p] == val && li[p] < idx);
            #pragma unroll
            for (int p = 9; p >= 1; p--)
                if (p > cnt) { lv[p] = lv[p - 1]; li[p] = li[p - 1]; }
            #pragma unroll
            for (int p = 0; p < 10; p++)
                if (p == cnt) { lv[p] = val; li[p] = idx; }
        }
    }

    int head = 0;
    for (int r = 0; r < 10; r++) {
        float cv = -FLT_MAX; int ci = 0x7fffffff;
        #pragma unroll
        for (int p = 0; p < 10; p++) if (p == head) { cv = lv[p]; ci = li[p]; }
        float bv = cv; int bi = ci; int bl = lane;
        for (int o = 16; o; o >>= 1) {
            float ov = __shfl_down_sync(0xffffffffu, bv, o);
            int oi = __shfl_down_sync(0xffffffffu, bi, o);
            int ol = __shfl_down_sync(0xffffffffu, bl, o);
            if (ov > bv || (ov == bv && oi < bi)) { bv = ov; bi = oi; bl = ol; }
        }
        bv = __shfl_sync(0xffffffffu, bv, 0);
        bi = __shfl_sync(0xffffffffu, bi, 0);
        bl = __shfl_sync(0xffffffffu, bl, 0);
        if (lane == bl) head++;
        if (lane == 0) { s_wv[wid * 10 + r] = bv; s_wi[wid * 10 + r] = bi; }
    }
    __syncthreads();
    if (wid == 0) {
        int hd = 0;
        for (int r = 0; r < 10; r++) {
            float cv = (hd < 10) ? s_wv[lane * 10 + hd] : -FLT_MAX;
            int ci = (hd < 10) ? s_wi[lane * 10 + hd] : 0x7fffffff;
            float bv = cv; int bi = ci; int bl = lane;
            for (int o = 16; o; o >>= 1) {
                float ov = __shfl_down_sync(0xffffffffu, bv, o);
                int oi = __shfl_down_sync(0xffffffffu, bi, o);
                int ol = __shfl_down_sync(0xffffffffu, bl, o);
                if (ov > bv || (ov == bv && oi < bi)) { bv = ov; bi = oi; bl = ol; }
            }
            bv = __shfl_sync(0xffffffffu, bv, 0);
            bi = __shfl_sync(0xffffffffu, bi, 0);
            bl = __shfl_sync(0xffffffffu, bl, 0);
            if (lane == bl) hd++;
            if (lane == 0) { s_tv[r] = bv; s_ti[r] = bi; }
        }
    }
    __syncthreads();

    if (tid < KB) {
        int ix = s_ti[tid];
        int r = ix / VV;
        int col = ix - r * VV;
        s_row[tid] = r; s_col[tid] = col;
        d_scores[tid] = s_tv[tid];
        d_fin[tid] = (s_fin[r] || (col == EOS_)) ? 1 : 0;
    }
    __syncthreads();

    int nxt = cur ^ 1;
    for (int i = tid; i < KB * (TT + 1); i += 1024) {
        int b = i / (TT + 1), p = i - b * (TT + 1);
        int val = (p == t + 1) ? s_col[b] : d_tok[cur][s_row[b] * (TT + 1) + p];
        d_tok[nxt][i] = val;
    }
    // fused gather: reorder states, build next-step xy
    for (int i = tid; i < KB * 1024; i += 1024) {
        int b = i >> 10, h2 = i & 1023;
        int r = s_row[b];
        d_h[i] = d_hn[r * 1024 + h2];
        d_c[i] = d_cn[r * 1024 + h2];
        d_xy[b * 2048 + 1024 + h2] = d_on[r * 1024 + h2];
        d_xy[b * 2048 + h2] = emb[(size_t)s_col[b] * EE + h2];
    }
}

// ---------------- output ----------------
__global__ void k_final(float* __restrict__ out, int n) {
    int tid = blockIdx.x * blockDim.x + threadIdx.x;
    int ntok = KB * (TT + 1);
    int fin = TT & 1;
    for (int i = tid; i < n; i += gridDim.x * blockDim.x) {
        if (i < ntok) out[i] = (float)d_tok[fin][i];
        else if (i < ntok + KB) out[i] = d_scores[i - ntok];
        else out[i] = 0.f;
    }
}

extern "C" void kernel_launch(void* const* d_in, const int* in_sizes, int n_in,
                              void* d_out, int out_size) {
    const float* enc  = (const float*)d_in[0];
    const float* h0   = (const float*)d_in[1];
    const float* c0   = (const float*)d_in[2];
    const float* emb  = (const float*)d_in[3];
    const float* W_ih = (const float*)d_in[4];
    const float* b_ih = (const float*)d_in[5];
    const float* W_hh = (const float*)d_in[6];
    const float* b_hh = (const float*)d_in[7];
    const float* W_at = (const float*)d_in[8];
    const float* W_cb = (const float*)d_in[9];
    const float* W_vb = (const float*)d_in[10];
    const int* srcl   = (const int*)d_in[11];

    k_init<<<48, 256>>>(h0, c0, emb);
    k_prep<<<dim3(HH / 16, SS / 16), 256>>>(enc, W_at, 2 * EE, 0);
    k_prep<<<dim3(HH / 16, SS / 16), 256>>>(enc, W_cb, 2 * EE + HH, 1);

    for (int t = 0; t < TT; t++) {
        int cur = t & 1;
        k_gates<<<128, 256>>>(W_ih, b_ih, W_hh, b_hh);
        k_attn<<<KB, 1024>>>(srcl);
        k_out<<<32, 256>>>(W_cb);
        k_logits<<<NLOG_BLK, 256>>>(W_vb);
        k_merge<<<1, 1024>>>(t, cur, emb);
    }
    k_final<<<1, 256>>>((float*)d_out, out_size);
}

// round 6
// speedup vs baseline: 1.0170x; 1.0170x over previous
#include <cuda_runtime.h>
#include <math.h>
#include <float.h>

#define KB 10
#define TT 70
#define SS 128
#define EE 1024
#define HH 1024
#define VV 32000
#define PAD_ 0
#define START_ 1
#define EOS_ 2
#define NEGF (-1000000000.0f)
#define NLOG_BLK 250   // logits blocks, 128 vocab rows each

// ---------------- device scratch ----------------
__device__ __align__(16) float d_keys[SS * HH];     // keys[s][h]
__device__ __align__(16) float d_Pt[HH * SS];       // Pt[j][s]
__device__ __align__(16) float d_h[KB * HH], d_c[KB * HH];
__device__ __align__(16) float d_xy[KB * 2048];     // [emb | prevOut] per beam
__device__ __align__(16) float d_hn[KB * HH], d_cn[KB * HH], d_on[KB * HH];
__device__ __align__(16) float d_alpha[KB * SS];
__device__ __align__(16) float d_gates[KB * 4 * HH];   // [k][row]
__device__ float d_scores[KB];
__device__ int d_fin[KB];
__device__ int d_tok[2][KB * (TT + 1)];
__device__ float d_pmax[NLOG_BLK * KB], d_psum[NLOG_BLK * KB];
__device__ float d_ptv[NLOG_BLK * KB * 10];
__device__ int   d_pti[NLOG_BLK * KB * 10];

__device__ __forceinline__ float sigm(float x) { return 1.f / (1.f + expf(-x)); }
__device__ __forceinline__ float dot4(float4 a, float4 b) {
    return a.x * b.x + a.y * b.y + a.z * b.z + a.w * b.w;
}

// ---------------- init ----------------
__global__ void k_init(const float* __restrict__ h0, const float* __restrict__ c0,
                       const float* __restrict__ emb) {
    int tid = blockIdx.x * blockDim.x + threadIdx.x;
    int nt = gridDim.x * blockDim.x;
    for (int i = tid; i < KB * HH; i += nt) {
        int h = i & 1023;
        d_h[i] = h0[h];
        d_c[i] = c0[h];
    }
    for (int i = tid; i < KB * 2048; i += nt) {
        int p = i & 2047;
        d_xy[i] = (p < 1024) ? emb[(size_t)START_ * EE + p] : 0.f;
    }
    for (int i = tid; i < KB * (TT + 1); i += nt)
        d_tok[0][i] = (i % (TT + 1) == 0) ? START_ : PAD_;
    if (tid < KB) { d_scores[tid] = (tid == 0) ? 0.f : NEGF; d_fin[tid] = 0; }
}

// ---------------- precompute keys / Pt ----------------
__global__ void k_prep(const float* __restrict__ enc, const float* __restrict__ W,
                       int ldw, int mode) {
    __shared__ float smW[16][129];
    __shared__ float smE[16][129];
    int j0 = blockIdx.x * 16, s0 = blockIdx.y * 16;
    int tid = threadIdx.x;
    int jj = tid & 15, ssn = tid >> 4;
    float acc = 0.f;
    for (int vc = 0; vc < 2 * EE; vc += 128) {
        for (int l = tid; l < 16 * 128; l += 256) {
            int r = l >> 7, cc = l & 127;
            smW[r][cc] = W[(size_t)(j0 + r) * ldw + vc + cc];
            smE[r][cc] = enc[(size_t)(s0 + r) * (2 * EE) + vc + cc];
        }
        __syncthreads();
        #pragma unroll
        for (int x = 0; x < 128; x++) acc += smW[jj][x] * smE[ssn][x];
        __syncthreads();
    }
    int j = j0 + jj, s = s0 + ssn;
    if (mode == 0) d_keys[s * HH + j] = acc;
    else           d_Pt[j * SS + s] = acc;
}

// ------- gates GEMV, R=4 rows/warp, 2-chunk unroll (8 LDG.128 in flight) -----
__global__ void __launch_bounds__(256, 1) k_gates(
        const float* __restrict__ W_ih, const float* __restrict__ b_ih,
        const float* __restrict__ W_hh, const float* __restrict__ b_hh) {
    int wid = threadIdx.x >> 5, lane = threadIdx.x & 31;
    int grp = blockIdx.x * 8 + wid;    // 0..1023
    int r0 = grp * 4;
    float acc[4][KB];
    #pragma unroll
    for (int r = 0; r < 4; r++)
        #pragma unroll
        for (int k = 0; k < KB; k++) acc[r][k] = 0.f;

    const float4* w0 = (const float4*)(W_ih + (size_t)(r0 + 0) * 2048);
    const float4* w1 = (const float4*)(W_ih + (size_t)(r0 + 1) * 2048);
    const float4* w2 = (const float4*)(W_ih + (size_t)(r0 + 2) * 2048);
    const float4* w3 = (const float4*)(W_ih + (size_t)(r0 + 3) * 2048);
    #pragma unroll
    for (int ch = 0; ch < 16; ch += 2) {
        int i0 = ch * 32 + lane, i1 = i0 + 32;
        float4 a0 = w0[i0], a1 = w1[i0], a2 = w2[i0], a3 = w3[i0];
        float4 b0 = w0[i1], b1 = w1[i1], b2 = w2[i1], b3 = w3[i1];
        #pragma unroll
        for (int k = 0; k < KB; k++) {
            float4 yv = ((const float4*)(d_xy + k * 2048))[i0];
            acc[0][k] += dot4(a0, yv); acc[1][k] += dot4(a1, yv);
            acc[2][k] += dot4(a2, yv); acc[3][k] += dot4(a3, yv);
        }
        #pragma unroll
        for (int k = 0; k < KB; k++) {
            float4 yv = ((const float4*)(d_xy + k * 2048))[i1];
            acc[0][k] += dot4(b0, yv); acc[1][k] += dot4(b1, yv);
            acc[2][k] += dot4(b2, yv); acc[3][k] += dot4(b3, yv);
        }
    }
    const float4* u0 = (const float4*)(W_hh + (size_t)(r0 + 0) * 1024);
    const float4* u1 = (const float4*)(W_hh + (size_t)(r0 + 1) * 1024);
    const float4* u2 = (const float4*)(W_hh + (size_t)(r0 + 2) * 1024);
    const float4* u3 = (const float4*)(W_hh + (size_t)(r0 + 3) * 1024);
    #pragma unroll
    for (int ch = 0; ch < 8; ch += 2) {
        int i0 = ch * 32 + lane, i1 = i0 + 32;
        float4 a0 = u0[i0], a1 = u1[i0], a2 = u2[i0], a3 = u3[i0];
        float4 b0 = u0[i1], b1 = u1[i1], b2 = u2[i1], b3 = u3[i1];
        #pragma unroll
        for (int k = 0; k < KB; k++) {
            float4 yv = ((const float4*)(d_h + k * 1024))[i0];
            acc[0][k] += dot4(a0, yv); acc[1][k] += dot4(a1, yv);
            acc[2][k] += dot4(a2, yv); acc[3][k] += dot4(a3, yv);
        }
        #pragma unroll
        for (int k = 0; k < KB; k++) {
            float4 yv = ((const float4*)(d_h + k * 1024))[i1];
            acc[0][k] += dot4(b0, yv); acc[1][k] += dot4(b1, yv);
            acc[2][k] += dot4(b2, yv); acc[3][k] += dot4(b3, yv);
        }
    }
    float bs0 = b_ih[r0] + b_hh[r0];
    float bs1 = b_ih[r0 + 1] + b_hh[r0 + 1];
    float bs2 = b_ih[r0 + 2] + b_hh[r0 + 2];
    float bs3 = b_ih[r0 + 3] + b_hh[r0 + 3];
    #pragma unroll
    for (int r = 0; r < 4; r++) {
        float bs = (r == 0) ? bs0 : (r == 1) ? bs1 : (r == 2) ? bs2 : bs3;
        #pragma unroll
        for (int k = 0; k < KB; k++) {
            float v = acc[r][k];
            for (int o = 16; o; o >>= 1) v += __shfl_down_sync(0xffffffffu, v, o);
            if (lane == 0) d_gates[k * 4096 + r0 + r] = v + bs;
        }
    }
}

// ------------- LSTM cell + attention scores + softmax (block per beam) -------
__global__ void __launch_bounds__(1024) k_attn(const int* __restrict__ src_len) {
    int k = blockIdx.x;
    int tid = threadIdx.x;
    __shared__ float s_h[1024];
    __shared__ float s_e[128];
    __shared__ float s_m, s_t;

    int j = tid;
    float gi = d_gates[k * 4096 + j];
    float gf = d_gates[k * 4096 + 1024 + j];
    float gg = d_gates[k * 4096 + 2048 + j];
    float go = d_gates[k * 4096 + 3072 + j];
    float cp = d_c[k * 1024 + j];
    float cn = sigm(gf) * cp + sigm(gi) * tanhf(gg);
    float hn = sigm(go) * tanhf(cn);
    d_cn[k * 1024 + j] = cn;
    d_hn[k * 1024 + j] = hn;
    s_h[j] = hn;
    __syncthreads();

    int wid = tid >> 5, lane = tid & 31;
    int slen = src_len[0];
    #pragma unroll
    for (int si = 0; si < 4; si++) {
        int s = wid * 4 + si;
        const float4* kr = (const float4*)(d_keys + s * 1024);
        const float4* hh = (const float4*)s_h;
        float a = 0.f;
        #pragma unroll
        for (int it = 0; it < 8; it++) {
            float4 xv = kr[it * 32 + lane];
            float4 yv = hh[it * 32 + lane];
            a += dot4(xv, yv);
        }
        for (int o = 16; o; o >>= 1) a += __shfl_down_sync(0xffffffffu, a, o);
        if (lane == 0) s_e[s] = (s >= slen) ? NEGF : a;
    }
    __syncthreads();
    if (wid == 0) {
        float v0 = s_e[lane], v1 = s_e[lane + 32], v2 = s_e[lane + 64], v3 = s_e[lane + 96];
        float m = fmaxf(fmaxf(v0, v1), fmaxf(v2, v3));
        for (int o = 16; o; o >>= 1) m = fmaxf(m, __shfl_xor_sync(0xffffffffu, m, o));
        float t = expf(v0 - m) + expf(v1 - m) + expf(v2 - m) + expf(v3 - m);
        for (int o = 16; o; o >>= 1) t += __shfl_xor_sync(0xffffffffu, t, o);
        if (lane == 0) { s_m = m; s_t = t; }
    }
    __syncthreads();
    if (tid < 128) d_alpha[k * 128 + tid] = expf(s_e[tid] - s_m) / s_t;
}

// ---- out[k][j] = tanh(alpha·Pt[j] + Wcomb2[j]·h_new), R=4 rows/warp ---------
__global__ void __launch_bounds__(256) k_out(const float* __restrict__ W_comb) {
    int wid = threadIdx.x >> 5, lane = threadIdx.x & 31;
    int grp = blockIdx.x * 8 + wid;   // 0..255
    int r0 = grp * 4;
    float acc[4][KB];
    #pragma unroll
    for (int r = 0; r < 4; r++)
        #pragma unroll
        for (int k = 0; k < KB; k++) acc[r][k] = 0.f;
    {
        float4 p0 = ((const float4*)(d_Pt + (r0 + 0) * 128))[lane];
        float4 p1 = ((const float4*)(d_Pt + (r0 + 1) * 128))[lane];
        float4 p2 = ((const float4*)(d_Pt + (r0 + 2) * 128))[lane];
        float4 p3 = ((const float4*)(d_Pt + (r0 + 3) * 128))[lane];
        #pragma unroll
        for (int k = 0; k < KB; k++) {
            float4 av = ((const float4*)(d_alpha + k * 128))[lane];
            acc[0][k] += dot4(p0, av); acc[1][k] += dot4(p1, av);
            acc[2][k] += dot4(p2, av); acc[3][k] += dot4(p3, av);
        }
    }
    const float4* w0 = (const float4*)(W_comb + (size_t)(r0 + 0) * 3072 + 2048);
    const float4* w1 = (const float4*)(W_comb + (size_t)(r0 + 1) * 3072 + 2048);
    const float4* w2 = (const float4*)(W_comb + (size_t)(r0 + 2) * 3072 + 2048);
    const float4* w3 = (const float4*)(W_comb + (size_t)(r0 + 3) * 3072 + 2048);
    #pragma unroll
    for (int ch = 0; ch < 8; ch += 2) {
        int i0 = ch * 32 + lane, i1 = i0 + 32;
        float4 a0 = w0[i0], a1 = w1[i0], a2 = w2[i0], a3 = w3[i0];
        float4 b0 = w0[i1], b1 = w1[i1], b2 = w2[i1], b3 = w3[i1];
        #pragma unroll
        for (int k = 0; k < KB; k++) {
            float4 yv = ((const float4*)(d_hn + k * 1024))[i0];
            acc[0][k] += dot4(a0, yv); acc[1][k] += dot4(a1, yv);
            acc[2][k] += dot4(a2, yv); acc[3][k] += dot4(a3, yv);
        }
        #pragma unroll
        for (int k = 0; k < KB; k++) {
            float4 yv = ((const float4*)(d_hn + k * 1024))[i1];
            acc[0][k] += dot4(b0, yv); acc[1][k] += dot4(b1, yv);
            acc[2][k] += dot4(b2, yv); acc[3][k] += dot4(b3, yv);
        }
    }
    #pragma unroll
    for (int r = 0; r < 4; r++)
        #pragma unroll
        for (int k = 0; k < KB; k++) {
            float v = acc[r][k];
            for (int o = 16; o; o >>= 1) v += __shfl_down_sync(0xffffffffu, v, o);
            if (lane == 0) d_on[k * HH + r0 + r] = tanhf(v);
        }
}

// ----- vocab logits (R=4 rows/warp) fused with per-block top-10 + lse -------
__global__ void __launch_bounds__(256) k_logits(const float* __restrict__ Wv) {
    __shared__ float s_on[KB * 1024];   // 40KB
    __shared__ float s_lg[KB][128];     // 5KB
    int tid = threadIdx.x;
    int wid = tid >> 5, lane = tid & 31;
    {
        const float4* src = (const float4*)d_on;
        float4* dst = (float4*)s_on;
        for (int i = tid; i < KB * 256; i += 256) dst[i] = src[i];
    }
    __syncthreads();
    int base = blockIdx.x * 128;

    for (int gg = 0; gg < 4; gg++) {
        int jloc = wid * 16 + gg * 4;          // 0..127 local row
        int r = base + jloc;
        float acc[4][KB];
        #pragma unroll
        for (int rr = 0; rr < 4; rr++)
            #pragma unroll
            for (int k = 0; k < KB; k++) acc[rr][k] = 0.f;
        const float4* w0 = (const float4*)(Wv + (size_t)r * 1024);
        const float4* w1 = w0 + 256;
        const float4* w2 = w0 + 512;
        const float4* w3 = w0 + 768;
        #pragma unroll
        for (int ch = 0; ch < 8; ch += 2) {
            int i0 = ch * 32 + lane, i1 = i0 + 32;
            float4 a0 = w0[i0], a1 = w1[i0], a2 = w2[i0], a3 = w3[i0];
            float4 b0 = w0[i1], b1 = w1[i1], b2 = w2[i1], b3 = w3[i1];
            #pragma unroll
            for (int k = 0; k < KB; k++) {
                float4 yv = ((const float4*)(s_on + k * 1024))[i0];
                acc[0][k] += dot4(a0, yv); acc[1][k] += dot4(a1, yv);
                acc[2][k] += dot4(a2, yv); acc[3][k] += dot4(a3, yv);
            }
            #pragma unroll
            for (int k = 0; k < KB; k++) {
                float4 yv = ((const float4*)(s_on + k * 1024))[i1];
                acc[0][k] += dot4(b0, yv); acc[1][k] += dot4(b1, yv);
                acc[2][k] += dot4(b2, yv); acc[3][k] += dot4(b3, yv);
            }
        }
        #pragma unroll
        for (int rr = 0; rr < 4; rr++)
            #pragma unroll
            for (int k = 0; k < KB; k++) {
                float v = acc[rr][k];
                for (int o = 16; o; o >>= 1) v += __shfl_down_sync(0xffffffffu, v, o);
                if (lane == 0) s_lg[k][jloc + rr] = v;
            }
    }
    __syncthreads();

    // per-beam block reduction: max, sumexp, top-10 (warp per beam)
    for (int k = wid; k < KB; k += 8) {
        float4 vv = ((const float4*)s_lg[k])[lane];
        float v0 = vv.x, v1 = vv.y, v2 = vv.z, v3 = vv.w;
        int gbase = k * VV + base + lane * 4;
        int i0 = gbase, i1 = gbase + 1, i2 = gbase + 2, i3 = gbase + 3;
        #define CSWAP(va, ia, vb, ib) { if (vb > va) { float tv = va; va = vb; vb = tv; int ti = ia; ia = ib; ib = ti; } }
        CSWAP(v0, i0, v1, i1); CSWAP(v2, i2, v3, i3);
        CSWAP(v0, i0, v2, i2); CSWAP(v1, i1, v3, i3);
        CSWAP(v1, i1, v2, i2);
        #undef CSWAP
        float m = v0;
        for (int o = 16; o; o >>= 1) m = fmaxf(m, __shfl_xor_sync(0xffffffffu, m, o));
        float ssum = expf(v0 - m) + expf(v1 - m) + expf(v2 - m) + expf(v3 - m);
        for (int o = 16; o; o >>= 1) ssum += __shfl_xor_sync(0xffffffffu, ssum, o);
        if (lane == 0) {
            d_pmax[blockIdx.x * KB + k] = m;
            d_psum[blockIdx.x * KB + k] = ssum;
        }
        int head = 0;
        for (int r2 = 0; r2 < 10; r2++) {
            float cv; int ci;
            if      (head == 0) { cv = v0; ci = i0; }
            else if (head == 1) { cv = v1; ci = i1; }
            else if (head == 2) { cv = v2; ci = i2; }
            else if (head == 3) { cv = v3; ci = i3; }
            else { cv = -FLT_MAX; ci = 0x7fffffff; }
            float bv = cv; int bi = ci; int bl = lane;
            for (int o = 16; o; o >>= 1) {
                float ov = __shfl_down_sync(0xffffffffu, bv, o);
                int oi = __shfl_down_sync(0xffffffffu, bi, o);
                int ol = __shfl_down_sync(0xffffffffu, bl, o);
                if (ov > bv || (ov == bv && oi < bi)) { bv = ov; bi = oi; bl = ol; }
            }
            bv = __shfl_sync(0xffffffffu, bv, 0);
            bi = __shfl_sync(0xffffffffu, bi, 0);
            bl = __shfl_sync(0xffffffffu, bl, 0);
            if (lane == bl) head++;
            if (lane == 0) {
                d_ptv[(blockIdx.x * KB + k) * 10 + r2] = bv;
                d_pti[(blockIdx.x * KB + k) * 10 + r2] = bi;
            }
        }
    }
}

// ------- merge partials: exact lse, global top-10, token update, gather ------
__global__ void __launch_bounds__(1024) k_merge(int t, int cur,
                                                const float* __restrict__ emb) {
    int tid = threadIdx.x;
    int wid = tid >> 5, lane = tid & 31;
    __shared__ float s_mx[KB], s_ls[KB], s_sc[KB];
    __shared__ int s_fin[KB];
    __shared__ float s_wv[320];
    __shared__ int s_wi[320];
    __shared__ float s_tv[KB];
    __shared__ int s_ti[KB];
    __shared__ int s_row[KB], s_col[KB];
    if (tid < KB) { s_sc[tid] = d_scores[tid]; s_fin[tid] = d_fin[tid]; }
    __syncthreads();

    if (wid < KB) {
        int k = wid;
        float m = -FLT_MAX;
        for (int b = lane; b < NLOG_BLK; b += 32) m = fmaxf(m, d_pmax[b * KB + k]);
        for (int o = 16; o; o >>= 1) m = fmaxf(m, __shfl_xor_sync(0xffffffffu, m, o));
        float s = 0.f;
        for (int b = lane; b < NLOG_BLK; b += 32)
            s += d_psum[b * KB + k] * expf(d_pmax[b * KB + k] - m);
        for (int o = 16; o; o >>= 1) s += __shfl_xor_sync(0xffffffffu, s, o);
        if (lane == 0) { s_mx[k] = m; s_ls[k] = logf(s); }
    }
    __syncthreads();

    float lv[10]; int li[10];
    #pragma unroll
    for (int p = 0; p < 10; p++) { lv[p] = -FLT_MAX; li[p] = 0x7fffffff; }

    const int NE = NLOG_BLK * KB * 10;
    for (int e = tid; e < NE; e += 1024) {
        int k = (e / 10) % KB;
        if (s_fin[k]) continue;
        float val = s_sc[k] + d_ptv[e] - s_mx[k] - s_ls[k];
        int idx = d_pti[e];
        if (val > lv[9] || (val == lv[9] && idx < li[9])) {
            int cnt = 0;
            #pragma unroll
            for (int p = 0; p < 10; p++)
                cnt += (lv[p] > val) || (lv[p] == val && li[p] < idx);
            #pragma unroll
            for (int p = 9; p >= 1; p--)
                if (p > cnt) { lv[p] = lv[p - 1]; li[p] = li[p - 1]; }
            #pragma unroll
            for (int p = 0; p < 10; p++)
                if (p == cnt) { lv[p] = val; li[p] = idx; }
        }
    }
    if (tid < KB && s_fin[tid]) {
        float val = s_sc[tid];
        int idx = tid * VV + PAD_;
        if (val > lv[9] || (val == lv[9] && idx < li[9])) {
            int cnt = 0;
            #pragma unroll
            for (int p = 0; p < 10; p++)
                cnt += (lv[p] > val) || (lv[p] == val && li[p] < idx);
            #pragma unroll
            for (int p = 9; p >= 1; p--)
                if (p > cnt) { lv[p] = lv[p - 1]; li[p] = li[p - 1]; }
            #pragma unroll
            for (int p = 0; p < 10; p++)
                if (p == cnt) { lv[p] = val; li[p] = idx; }
        }
    }

    int head = 0;
    for (int r = 0; r < 10; r++) {
        float cv = -FLT_MAX; int ci = 0x7fffffff;
        #pragma unroll
        for (int p = 0; p < 10; p++) if (p == head) { cv = lv[p]; ci = li[p]; }
        float bv = cv; int bi = ci; int bl = lane;
        for (int o = 16; o; o >>= 1) {
            float ov = __shfl_down_sync(0xffffffffu, bv, o);
            int oi = __shfl_down_sync(0xffffffffu, bi, o);
            int ol = __shfl_down_sync(0xffffffffu, bl, o);
            if (ov > bv || (ov == bv && oi < bi)) { bv = ov; bi = oi; bl = ol; }
        }
        bv = __shfl_sync(0xffffffffu, bv, 0);
        bi = __shfl_sync(0xffffffffu, bi, 0);
        bl = __shfl_sync(0xffffffffu, bl, 0);
        if (lane == bl) head++;
        if (lane == 0) { s_wv[wid * 10 + r] = bv; s_wi[wid * 10 + r] = bi; }
    }
    __syncthreads();
    if (wid == 0) {
        int hd = 0;
        for (int r = 0; r < 10; r++) {
            float cv = (hd < 10) ? s_wv[lane * 10 + hd] : -FLT_MAX;
            int ci = (hd < 10) ? s_wi[lane * 10 + hd] : 0x7fffffff;
            float bv = cv; int bi = ci; int bl = lane;
            for (int o = 16; o; o >>= 1) {
                float ov = __shfl_down_sync(0xffffffffu, bv, o);
                int oi = __shfl_down_sync(0xffffffffu, bi, o);
                int ol = __shfl_down_sync(0xffffffffu, bl, o);
                if (ov > bv || (ov == bv && oi < bi)) { bv = ov; bi = oi; bl = ol; }
            }
            bv = __shfl_sync(0xffffffffu, bv, 0);
            bi = __shfl_sync(0xffffffffu, bi, 0);
            bl = __shfl_sync(0xffffffffu, bl, 0);
            if (lane == bl) hd++;
            if (lane == 0) { s_tv[r] = bv; s_ti[r] = bi; }
        }
    }
    __syncthreads();

    if (tid < KB) {
        int ix = s_ti[tid];
        int r = ix / VV;
        int col = ix - r * VV;
        s_row[tid] = r; s_col[tid] = col;
        d_scores[tid] = s_tv[tid];
        d_fin[tid] = (s_fin[r] || (col == EOS_)) ? 1 : 0;
    }
    __syncthreads();

    int nxt = cur ^ 1;
    for (int i = tid; i < KB * (TT + 1); i += 1024) {
        int b = i / (TT + 1), p = i - b * (TT + 1);
        int val = (p == t + 1) ? s_col[b] : d_tok[cur][s_row[b] * (TT + 1) + p];
        d_tok[nxt][i] = val;
    }
    // fused gather: reorder states, build next-step xy
    for (int i = tid; i < KB * 1024; i += 1024) {
        int b = i >> 10, h2 = i & 1023;
        int r = s_row[b];
        d_h[i] = d_hn[r * 1024 + h2];
        d_c[i] = d_cn[r * 1024 + h2];
        d_xy[b * 2048 + 1024 + h2] = d_on[r * 1024 + h2];
        d_xy[b * 2048 + h2] = emb[(size_t)s_col[b] * EE + h2];
    }
}

// ---------------- output ----------------
__global__ void k_final(float* __restrict__ out, int n) {
    int tid = blockIdx.x * blockDim.x + threadIdx.x;
    int ntok = KB * (TT + 1);
    int fin = TT & 1;
    for (int i = tid; i < n; i += gridDim.x * blockDim.x) {
        if (i < ntok) out[i] = (float)d_tok[fin][i];
        else if (i < ntok + KB) out[i] = d_scores[i - ntok];
        else out[i] = 0.f;
    }
}

extern "C" void kernel_launch(void* const* d_in, const int* in_sizes, int n_in,
                              void* d_out, int out_size) {
    const float* enc  = (const float*)d_in[0];
    const float* h0   = (const float*)d_in[1];
    const float* c0   = (const float*)d_in[2];
    const float* emb  = (const float*)d_in[3];
    const float* W_ih = (const float*)d_in[4];
    const float* b_ih = (const float*)d_in[5];
    const float* W_hh = (const float*)d_in[6];
    const float* b_hh = (const float*)d_in[7];
    const float* W_at = (const float*)d_in[8];
    const float* W_cb = (const float*)d_in[9];
    const float* W_vb = (const float*)d_in[10];
    const int* srcl   = (const int*)d_in[11];

    k_init<<<48, 256>>>(h0, c0, emb);
    k_prep<<<dim3(HH / 16, SS / 16), 256>>>(enc, W_at, 2 * EE, 0);
    k_prep<<<dim3(HH / 16, SS / 16), 256>>>(enc, W_cb, 2 * EE + HH, 1);

    for (int t = 0; t < TT; t++) {
        int cur = t & 1;
        k_gates<<<128, 256>>>(W_ih, b_ih, W_hh, b_hh);
        k_attn<<<KB, 1024>>>(srcl);
        k_out<<<32, 256>>>(W_cb);
        k_logits<<<NLOG_BLK, 256>>>(W_vb);
        k_merge<<<1, 1024>>>(t, cur, emb);
    }
    k_final<<<1, 256>>>((float*)d_out, out_size);
}

// round 12
// speedup vs baseline: 1.6735x; 1.6455x over previous
#include <cuda_runtime.h>
#include <math.h>
#include <float.h>

#define KB 10
#define TT 70
#define SS 128
#define EE 1024
#define HH 1024
#define VV 32000
#define PAD_ 0
#define START_ 1
#define EOS_ 2
#define NEGF (-1000000000.0f)
#define NLOG_BLK 250

__device__ __align__(16) float d_keys[SS * HH];
__device__ __align__(16) float d_Pt[HH * SS];
__device__ __align__(16) float d_h[KB * HH], d_c[KB * HH];
__device__ __align__(16) float d_xy[KB * 2048];
__device__ __align__(16) float d_hn[KB * HH], d_cn[KB * HH], d_on[KB * HH];
__device__ __align__(16) float d_alpha[KB * SS];
__device__ __align__(16) float d_gates[KB * 4 * HH];
__device__ float d_scores[KB];
__device__ int d_fin[KB];
__device__ int d_tok[2][KB * (TT + 1)];
__device__ float d_pmax[NLOG_BLK * KB], d_psum[NLOG_BLK * KB];
__device__ float d_ptv[NLOG_BLK * KB * 10];
__device__ int   d_pti[NLOG_BLK * KB * 10];
__device__ float d_btv[KB * 10];
__device__ int   d_bti[KB * 10];
__device__ float d_mx[KB], d_lse[KB];

__device__ __forceinline__ float sigm(float x) { return 1.f / (1.f + expf(-x)); }
__device__ __forceinline__ float dot4(float4 a, float4 b) {
    return a.x * b.x + a.y * b.y + a.z * b.z + a.w * b.w;
}
__device__ __forceinline__ void ins10(float val, int idx, float lv[10], int li[10]) {
    if (val > lv[9] || (val == lv[9] && idx < li[9])) {
        int cnt = 0;
        #pragma unroll
        for (int p = 0; p < 10; p++) cnt += (lv[p] > val) || (lv[p] == val && li[p] < idx);
        #pragma unroll
        for (int p = 9; p >= 1; p--) if (p > cnt) { lv[p] = lv[p - 1]; li[p] = li[p - 1]; }
        #pragma unroll
        for (int p = 0; p < 10; p++) if (p == cnt) { lv[p] = val; li[p] = idx; }
    }
}
// merge 32 per-lane sorted lists (desc val, asc idx) -> top-10; lane0 writes outv/outi
__device__ __forceinline__ void merge32(float lv[10], int li[10], int lane,
                                        float* outv, int* outi) {
    int head = 0;
    for (int r = 0; r < 10; r++) {
        float cv = -FLT_MAX; int ci = 0x7fffffff;
        #pragma unroll
        for (int p = 0; p < 10; p++) if (p == head) { cv = lv[p]; ci = li[p]; }
        float bv = cv; int bi = ci; int bl = lane;
        for (int o = 16; o; o >>= 1) {
            float ov = __shfl_down_sync(0xffffffffu, bv, o);
            int oi = __shfl_down_sync(0xffffffffu, bi, o);
            int ol = __shfl_down_sync(0xffffffffu, bl, o);
            if (ov > bv || (ov == bv && oi < bi)) { bv = ov; bi = oi; bl = ol; }
        }
        bv = __shfl_sync(0xffffffffu, bv, 0);
        bi = __shfl_sync(0xffffffffu, bi, 0);
        bl = __shfl_sync(0xffffffffu, bl, 0);
        if (lane == bl) head++;
        if (lane == 0) { outv[r] = bv; outi[r] = bi; }
    }
}

__global__ void k_init(const float* __restrict__ h0, const float* __restrict__ c0,
                       const float* __restrict__ emb) {
    int tid = blockIdx.x * blockDim.x + threadIdx.x;
    int nt = gridDim.x * blockDim.x;
    for (int i = tid; i < KB * HH; i += nt) {
        int h = i & 1023;
        d_h[i] = h0[h];
        d_c[i] = c0[h];
    }
    for (int i = tid; i < KB * 2048; i += nt) {
        int p = i & 2047;
        d_xy[i] = (p < 1024) ? emb[(size_t)START_ * EE + p] : 0.f;
    }
    for (int i = tid; i < KB * (TT + 1); i += nt)
        d_tok[0][i] = (i % (TT + 1) == 0) ? START_ : PAD_;
    if (tid < KB) { d_scores[tid] = (tid == 0) ? 0.f : NEGF; d_fin[tid] = 0; }
}

__global__ void k_prep(const float* __restrict__ enc, const float* __restrict__ W,
                       int ldw, int mode) {
    __shared__ float smW[16][129];
    __shared__ float smE[16][129];
    int j0 = blockIdx.x * 16, s0 = blockIdx.y * 16;
    int tid = threadIdx.x;
    int jj = tid & 15, ssn = tid >> 4;
    float acc = 0.f;
    for (int vc = 0; vc < 2 * EE; vc += 128) {
        for (int l = tid; l < 16 * 128; l += 256) {
            int r = l >> 7, cc = l & 127;
            smW[r][cc] = W[(size_t)(j0 + r) * ldw + vc + cc];
            smE[r][cc] = enc[(size_t)(s0 + r) * (2 * EE) + vc + cc];
        }
        __syncthreads();
        #pragma unroll
        for (int x = 0; x < 128; x++) acc += smW[jj][x] * smE[ssn][x];
        __syncthreads();
    }
    int j = j0 + jj, s = s0 + ssn;
    if (mode == 0) d_keys[s * HH + j] = acc;
    else           d_Pt[j * SS + s] = acc;
}

// ---- gates GEMV: R2-exact (warp per 2 rows, float4, 2-chunk unroll) ----
__global__ void __launch_bounds__(256) k_gates(
        const float* __restrict__ W_ih, const float* __restrict__ b_ih,
        const float* __restrict__ W_hh, const float* __restrict__ b_hh) {
    int wid = threadIdx.x >> 5, lane = threadIdx.x & 31;
    int pair = blockIdx.x * 8 + wid;
    int r0 = pair * 2, r1 = r0 + 1;
    float acc[2][KB];
    #pragma unroll
    for (int r = 0; r < 2; r++)
        #pragma unroll
        for (int k = 0; k < KB; k++) acc[r][k] = 0.f;

    const float4* wa = (const float4*)(W_ih + (size_t)r0 * 2048);
    const float4* wb = (const float4*)(W_ih + (size_t)r1 * 2048);
    #pragma unroll 4
    for (int it = 0; it < 16; it++) {
        int ix = it * 32 + lane;
        float4 a0 = wa[ix], a1 = wb[ix];
        #pragma unroll
        for (int k = 0; k < KB; k++) {
            float4 y = ((const float4*)(d_xy + k * 2048))[ix];
            acc[0][k] += dot4(a0, y);
            acc[1][k] += dot4(a1, y);
        }
    }
    const float4* ua = (const float4*)(W_hh + (size_t)r0 * 1024);
    const float4* ub = (const float4*)(W_hh + (size_t)r1 * 1024);
    #pragma unroll 4
    for (int it = 0; it < 8; it++) {
        int ix = it * 32 + lane;
        float4 a0 = ua[ix], a1 = ub[ix];
        #pragma unroll
        for (int k = 0; k < KB; k++) {
            float4 y = ((const float4*)(d_h + k * 1024))[ix];
            acc[0][k] += dot4(a0, y);
            acc[1][k] += dot4(a1, y);
        }
    }
    float bs0 = b_ih[r0] + b_hh[r0];
    float bs1 = b_ih[r1] + b_hh[r1];
    #pragma unroll
    for (int k = 0; k < KB; k++) {
        float v0 = acc[0][k], v1 = acc[1][k];
        for (int o = 16; o; o >>= 1) {
            v0 += __shfl_down_sync(0xffffffffu, v0, o);
            v1 += __shfl_down_sync(0xffffffffu, v1, o);
        }
        if (lane == 0) {
            d_gates[k * 4096 + r0] = v0 + bs0;
            d_gates[k * 4096 + r1] = v1 + bs1;
        }
    }
}

__global__ void __launch_bounds__(1024) k_attn(const int* __restrict__ src_len) {
    int k = blockIdx.x;
    int tid = threadIdx.x;
    __shared__ float s_h[1024];
    __shared__ float s_e[128];
    __shared__ float s_m, s_t;
    int j = tid;
    float gi = d_gates[k * 4096 + j];
    float gf = d_gates[k * 4096 + 1024 + j];
    float gg = d_gates[k * 4096 + 2048 + j];
    float go = d_gates[k * 4096 + 3072 + j];
    float cp = d_c[k * 1024 + j];
    float cn = sigm(gf) * cp + sigm(gi) * tanhf(gg);
    float hn = sigm(go) * tanhf(cn);
    d_cn[k * 1024 + j] = cn;
    d_hn[k * 1024 + j] = hn;
    s_h[j] = hn;
    __syncthreads();
    int wid = tid >> 5, lane = tid & 31;
    int slen = src_len[0];
    #pragma unroll
    for (int si = 0; si < 4; si++) {
        int s = wid * 4 + si;
        const float4* kr = (const float4*)(d_keys + s * 1024);
        const float4* hh = (const float4*)s_h;
        float a = 0.f;
        #pragma unroll
        for (int it = 0; it < 8; it++)
            a += dot4(kr[it * 32 + lane], hh[it * 32 + lane]);
        for (int o = 16; o; o >>= 1) a += __shfl_down_sync(0xffffffffu, a, o);
        if (lane == 0) s_e[s] = (s >= slen) ? NEGF : a;
    }
    __syncthreads();
    if (wid == 0) {
        float v0 = s_e[lane], v1 = s_e[lane + 32], v2 = s_e[lane + 64], v3 = s_e[lane + 96];
        float m = fmaxf(fmaxf(v0, v1), fmaxf(v2, v3));
        for (int o = 16; o; o >>= 1) m = fmaxf(m, __shfl_xor_sync(0xffffffffu, m, o));
        float t = expf(v0 - m) + expf(v1 - m) + expf(v2 - m) + expf(v3 - m);
        for (int o = 16; o; o >>= 1) t += __shfl_xor_sync(0xffffffffu, t, o);
        if (lane == 0) { s_m = m; s_t = t; }
    }
    __syncthreads();
    if (tid < 128) d_alpha[k * 128 + tid] = expf(s_e[tid] - s_m) / s_t;
}

__global__ void __launch_bounds__(128) k_out(const float* __restrict__ W_comb) {
    int j = blockIdx.x, tid = threadIdx.x;
    float acc[KB];
    #pragma unroll
    for (int k = 0; k < KB; k++) acc[k] = 0.f;
    {
        float p = d_Pt[j * 128 + tid];
        #pragma unroll
        for (int k = 0; k < KB; k++) acc[k] += d_alpha[k * 128 + tid] * p;
    }
    const float4* w4 = (const float4*)(W_comb + (size_t)j * 3072 + 2048);
    #pragma unroll
    for (int it = 0; it < 2; it++) {
        int ix = it * 128 + tid;
        float4 a = w4[ix];
        #pragma unroll
        for (int k = 0; k < KB; k++)
            acc[k] += dot4(a, ((const float4*)(d_hn + k * 1024))[ix]);
    }
    __shared__ float sp[4][KB];
    int wid = tid >> 5, lane = tid & 31;
    #pragma unroll
    for (int k = 0; k < KB; k++) {
        float v = acc[k];
        for (int o = 16; o; o >>= 1) v += __shfl_down_sync(0xffffffffu, v, o);
        if (lane == 0) sp[wid][k] = v;
    }
    __syncthreads();
    if (tid < KB) {
        float v = sp[0][tid] + sp[1][tid] + sp[2][tid] + sp[3][tid];
        d_on[tid * HH + j] = tanhf(v);
    }
}

// ---- vocab logits: R2-exact, fused per-block stats + top-10 ----
__global__ void __launch_bounds__(256) k_logits(const float* __restrict__ Wv) {
    __shared__ float s_on[KB * 1024];
    __shared__ float s_lg[KB][128];
    int tid = threadIdx.x;
    int wid = tid >> 5, lane = tid & 31;
    {
        const float4* src = (const float4*)d_on;
        float4* dst = (float4*)s_on;
        for (int i = tid; i < KB * 256; i += 256) dst[i] = src[i];
    }
    __syncthreads();
    int base = blockIdx.x * 128;

    for (int qq = 0; qq < 4; qq++) {
        int q = wid * 4 + qq;
        int r = base + q * 4;
        float acc[4][KB];
        #pragma unroll
        for (int rr = 0; rr < 4; rr++)
            #pragma unroll
            for (int k = 0; k < KB; k++) acc[rr][k] = 0.f;
        const float4* w0 = (const float4*)(Wv + (size_t)r * 1024);
        const float4* w1 = w0 + 256;
        const float4* w2 = w0 + 512;
        const float4* w3 = w0 + 768;
        #pragma unroll
        for (int it = 0; it < 8; it++) {
            int ix = it * 32 + lane;
            float4 a0 = w0[ix], a1 = w1[ix], a2 = w2[ix], a3 = w3[ix];
            #pragma unroll
            for (int k = 0; k < KB; k++) {
                float4 o = ((const float4*)(s_on + k * 1024))[ix];
                acc[0][k] += dot4(a0, o); acc[1][k] += dot4(a1, o);
                acc[2][k] += dot4(a2, o); acc[3][k] += dot4(a3, o);
            }
        }
        #pragma unroll
        for (int rr = 0; rr < 4; rr++)
            #pragma unroll
            for (int k = 0; k < KB; k++) {
                float v = acc[rr][k];
                for (int o = 16; o; o >>= 1) v += __shfl_down_sync(0xffffffffu, v, o);
                if (lane == 0) s_lg[k][q * 4 + rr] = v;
            }
    }
    __syncthreads();

    for (int k = wid; k < KB; k += 8) {
        float4 vv = ((const float4*)s_lg[k])[lane];
        float v0 = vv.x, v1 = vv.y, v2 = vv.z, v3 = vv.w;
        int gbase = k * VV + base + lane * 4;
        int i0 = gbase, i1 = gbase + 1, i2 = gbase + 2, i3 = gbase + 3;
        #define CSWAP(va, ia, vb, ib) { if (vb > va) { float tv = va; va = vb; vb = tv; int ti = ia; ia = ib; ib = ti; } }
        CSWAP(v0, i0, v1, i1); CSWAP(v2, i2, v3, i3);
        CSWAP(v0, i0, v2, i2); CSWAP(v1, i1, v3, i3);
        CSWAP(v1, i1, v2, i2);
        #undef CSWAP
        float m = v0;
        for (int o = 16; o; o >>= 1) m = fmaxf(m, __shfl_xor_sync(0xffffffffu, m, o));
        float ssum = expf(v0 - m) + expf(v1 - m) + expf(v2 - m) + expf(v3 - m);
        for (int o = 16; o; o >>= 1) ssum += __shfl_xor_sync(0xffffffffu, ssum, o);
        if (lane == 0) {
            d_pmax[blockIdx.x * KB + k] = m;
            d_psum[blockIdx.x * KB + k] = ssum;
        }
        float lv[10]; int li[10];
        lv[0] = v0; li[0] = i0; lv[1] = v1; li[1] = i1;
        lv[2] = v2; li[2] = i2; lv[3] = v3; li[3] = i3;
        #pragma unroll
        for (int p = 4; p < 10; p++) { lv[p] = -FLT_MAX; li[p] = 0x7fffffff; }
        merge32(lv, li, lane,
                &d_ptv[(blockIdx.x * KB + k) * 10], &d_pti[(blockIdx.x * KB + k) * 10]);
    }
}

// ---- NEW: per-beam reduction of 250 partial lists + exact max/lse ----
__global__ void __launch_bounds__(256) k_reduce() {
    int k = blockIdx.x;
    int tid = threadIdx.x, wid = tid >> 5, lane = tid & 31;
    __shared__ float s_red[8];
    __shared__ float s_m;
    __shared__ float s_wv[8 * 10];
    __shared__ int s_wi[8 * 10];

    // max over block partials
    float m = -FLT_MAX;
    for (int b = tid; b < NLOG_BLK; b += 256) m = fmaxf(m, d_pmax[b * KB + k]);
    for (int o = 16; o; o >>= 1) m = fmaxf(m, __shfl_xor_sync(0xffffffffu, m, o));
    if (lane == 0) s_red[wid] = m;
    __syncthreads();
    if (tid == 0) {
        float v = -FLT_MAX;
        #pragma unroll
        for (int i = 0; i < 8; i++) v = fmaxf(v, s_red[i]);
        s_m = v;
    }
    __syncthreads();
    float mm = s_m;
    float s = 0.f;
    for (int b = tid; b < NLOG_BLK; b += 256)
        s += d_psum[b * KB + k] * expf(d_pmax[b * KB + k] - mm);
    for (int o = 16; o; o >>= 1) s += __shfl_xor_sync(0xffffffffu, s, o);
    if (lane == 0) s_red[wid] = s;
    __syncthreads();
    if (tid == 0) {
        float v = 0.f;
        #pragma unroll
        for (int i = 0; i < 8; i++) v += s_red[i];
        d_mx[k] = mm;
        d_lse[k] = logf(v);
    }

    // top-10 over 2500 partial entries
    float lv[10]; int li[10];
    #pragma unroll
    for (int p = 0; p < 10; p++) { lv[p] = -FLT_MAX; li[p] = 0x7fffffff; }
    for (int e = tid; e < NLOG_BLK * 10; e += 256) {
        int blk = e / 10, r = e - blk * 10;
        ins10(d_ptv[(blk * KB + k) * 10 + r], d_pti[(blk * KB + k) * 10 + r], lv, li);
    }
    merge32(lv, li, lane, &s_wv[wid * 10], &s_wi[wid * 10]);
    __syncthreads();
    if (wid == 0) {
        float lv2[10]; int li2[10];
        #pragma unroll
        for (int p = 0; p < 10; p++) { lv2[p] = -FLT_MAX; li2[p] = 0x7fffffff; }
        if (lane < 8)
            #pragma unroll
            for (int p = 0; p < 10; p++) { lv2[p] = s_wv[lane * 10 + p]; li2[p] = s_wi[lane * 10 + p]; }
        merge32(lv2, li2, lane, &d_btv[k * 10], &d_bti[k * 10]);
    }
}

// ---- merge 100 candidates, token update, fused gather (R4-proven) ----
__global__ void __launch_bounds__(1024) k_merge(int t, int cur,
                                                const float* __restrict__ emb) {
    int tid = threadIdx.x;
    int wid = tid >> 5, lane = tid & 31;
    __shared__ float s_mx[KB], s_ls[KB], s_sc[KB];
    __shared__ int s_fin[KB];
    __shared__ float s_wv[320];
    __shared__ int s_wi[320];
    __shared__ float s_tv[KB];
    __shared__ int s_ti[KB];
    __shared__ int s_row[KB], s_col[KB];
    if (tid < KB) {
        s_sc[tid] = d_scores[tid]; s_fin[tid] = d_fin[tid];
        s_mx[tid] = d_mx[tid]; s_ls[tid] = d_lse[tid];
    }
    __syncthreads();

    float lv[10]; int li[10];
    #pragma unroll
    for (int p = 0; p < 10; p++) { lv[p] = -FLT_MAX; li[p] = 0x7fffffff; }
    if (tid < KB * 10) {
        int k = tid / 10;
        if (!s_fin[k])
            ins10(s_sc[k] + d_btv[tid] - s_mx[k] - s_ls[k], d_bti[tid], lv, li);
    }
    if (tid >= 512 && tid - 512 < KB && s_fin[tid - 512])
        ins10(s_sc[tid - 512], (tid - 512) * VV + PAD_, lv, li);

    merge32(lv, li, lane, &s_wv[wid * 10], &s_wi[wid * 10]);
    __syncthreads();
    if (wid == 0) {
        float lv2[10]; int li2[10];
        int hd = 0;
        for (int r = 0; r < 10; r++) {
            float cv = (hd < 10) ? s_wv[lane * 10 + hd] : -FLT_MAX;
            int ci = (hd < 10) ? s_wi[lane * 10 + hd] : 0x7fffffff;
            float bv = cv; int bi = ci; int bl = lane;
            for (int o = 16; o; o >>= 1) {
                float ov = __shfl_down_sync(0xffffffffu, bv, o);
                int oi = __shfl_down_sync(0xffffffffu, bi, o);
                int ol = __shfl_down_sync(0xffffffffu, bl, o);
                if (ov > bv || (ov == bv && oi < bi)) { bv = ov; bi = oi; bl = ol; }
            }
            bv = __shfl_sync(0xffffffffu, bv, 0);
            bi = __shfl_sync(0xffffffffu, bi, 0);
            bl = __shfl_sync(0xffffffffu, bl, 0);
            if (lane == bl) hd++;
            if (lane == 0) { s_tv[r] = bv; s_ti[r] = bi; }
        }
        (void)lv2; (void)li2;
    }
    __syncthreads();

    if (tid < KB) {
        int ix = s_ti[tid];
        int r = ix / VV;
        int col = ix - r * VV;
        s_row[tid] = r; s_col[tid] = col;
        d_scores[tid] = s_tv[tid];
        d_fin[tid] = (s_fin[r] || (col == EOS_)) ? 1 : 0;
    }
    __syncthreads();

    int nxt = cur ^ 1;
    for (int i = tid; i < KB * (TT + 1); i += 1024) {
        int b = i / (TT + 1), p = i - b * (TT + 1);
        int val = (p == t + 1) ? s_col[b] : d_tok[cur][s_row[b] * (TT + 1) + p];
        d_tok[nxt][i] = val;
    }
    for (int i = tid; i < KB * 1024; i += 1024) {
        int b = i >> 10, h2 = i & 1023;
        int r = s_row[b];
        d_h[i] = d_hn[r * 1024 + h2];
        d_c[i] = d_cn[r * 1024 + h2];
        d_xy[b * 2048 + 1024 + h2] = d_on[r * 1024 + h2];
        d_xy[b * 2048 + h2] = emb[(size_t)s_col[b] * EE + h2];
    }
}

__global__ void k_final(float* __restrict__ out, int n) {
    int tid = blockIdx.x * blockDim.x + threadIdx.x;
    int ntok = KB * (TT + 1);
    int fin = TT & 1;
    for (int i = tid; i < n; i += gridDim.x * blockDim.x) {
        if (i < ntok) out[i] = (float)d_tok[fin][i];
        else if (i < ntok + KB) out[i] = d_scores[i - ntok];
        else out[i] = 0.f;
    }
}

extern "C" void kernel_launch(void* const* d_in, const int* in_sizes, int n_in,
                              void* d_out, int out_size) {
    const float* enc  = (const float*)d_in[0];
    const float* h0   = (const float*)d_in[1];
    const float* c0   = (const float*)d_in[2];
    const float* emb  = (const float*)d_in[3];
    const float* W_ih = (const float*)d_in[4];
    const float* b_ih = (const float*)d_in[5];
    const float* W_hh = (const float*)d_in[6];
    const float* b_hh = (const float*)d_in[7];
    const float* W_at = (const float*)d_in[8];
    const float* W_cb = (const float*)d_in[9];
    const float* W_vb = (const float*)d_in[10];
    const int* srcl   = (const int*)d_in[11];

    k_init<<<48, 256>>>(h0, c0, emb);
    k_prep<<<dim3(HH / 16, SS / 16), 256>>>(enc, W_at, 2 * EE, 0);
    k_prep<<<dim3(HH / 16, SS / 16), 256>>>(enc, W_cb, 2 * EE + HH, 1);

    for (int t = 0; t < TT; t++) {
        int cur = t & 1;
        k_gates<<<256, 256>>>(W_ih, b_ih, W_hh, b_hh);
        k_attn<<<KB, 1024>>>(srcl);
        k_out<<<HH, 128>>>(W_cb);
        k_logits<<<NLOG_BLK, 256>>>(W_vb);
        k_reduce<<<KB, 256>>>();
        k_merge<<<1, 1024>>>(t, cur, emb);
    }
    k_final<<<1, 256>>>((float*)d_out, out_size);
}

// round 14
// speedup vs baseline: 2.2647x; 1.3533x over previous
#include <cuda_runtime.h>
#include <math.h>
#include <float.h>

#define KB 10
#define TT 70
#define SS 128
#define EE 1024
#define HH 1024
#define VV 32000
#define PAD_ 0
#define START_ 1
#define EOS_ 2
#define NEGF (-1000000000.0f)
#define NLOG_BLK 1000

__device__ __align__(16) float d_keys[SS * HH];
__device__ __align__(16) float d_Pt[HH * SS];
__device__ __align__(16) float d_h[KB * HH], d_c[KB * HH];
__device__ __align__(16) float d_xy[KB * 2048];
__device__ __align__(16) float d_hn[KB * HH], d_cn[KB * HH], d_on[KB * HH];
__device__ __align__(16) float d_alpha[KB * SS];
__device__ __align__(16) float d_gp[4][KB * 4 * HH];
__device__ float d_scores[KB];
__device__ int d_fin[KB];
__device__ int d_tok[2][KB * (TT + 1)];
__device__ float d_pmax[NLOG_BLK * KB], d_psum[NLOG_BLK * KB];
__device__ float d_ptv[NLOG_BLK * KB * 10];
__device__ int   d_pti[NLOG_BLK * KB * 10];
__device__ float d_btv[KB * 10];
__device__ int   d_bti[KB * 10];
__device__ float d_mx[KB], d_lse[KB];

__device__ __forceinline__ float sigm(float x) { return 1.f / (1.f + expf(-x)); }
__device__ __forceinline__ float dot4(float4 a, float4 b) {
    return a.x * b.x + a.y * b.y + a.z * b.z + a.w * b.w;
}
__device__ __forceinline__ void ins10(float val, int idx, float lv[10], int li[10]) {
    if (val > lv[9] || (val == lv[9] && idx < li[9])) {
        int cnt = 0;
        #pragma unroll
        for (int p = 0; p < 10; p++) cnt += (lv[p] > val) || (lv[p] == val && li[p] < idx);
        #pragma unroll
        for (int p = 9; p >= 1; p--) if (p > cnt) { lv[p] = lv[p - 1]; li[p] = li[p - 1]; }
        #pragma unroll
        for (int p = 0; p < 10; p++) if (p == cnt) { lv[p] = val; li[p] = idx; }
    }
}
__device__ __forceinline__ void merge32(float lv[10], int li[10], int lane,
                                        float* outv, int* outi) {
    int head = 0;
    for (int r = 0; r < 10; r++) {
        float cv = -FLT_MAX; int ci = 0x7fffffff;
        #pragma unroll
        for (int p = 0; p < 10; p++) if (p == head) { cv = lv[p]; ci = li[p]; }
        float bv = cv; int bi = ci; int bl = lane;
        for (int o = 16; o; o >>= 1) {
            float ov = __shfl_down_sync(0xffffffffu, bv, o);
            int oi = __shfl_down_sync(0xffffffffu, bi, o);
            int ol = __shfl_down_sync(0xffffffffu, bl, o);
            if (ov > bv || (ov == bv && oi < bi)) { bv = ov; bi = oi; bl = ol; }
        }
        bv = __shfl_sync(0xffffffffu, bv, 0);
        bi = __shfl_sync(0xffffffffu, bi, 0);
        bl = __shfl_sync(0xffffffffu, bl, 0);
        if (lane == bl) head++;
        if (lane == 0) { outv[r] = bv; outi[r] = bi; }
    }
}

__global__ void k_init(const float* __restrict__ h0, const float* __restrict__ c0,
                       const float* __restrict__ emb) {
    int tid = blockIdx.x * blockDim.x + threadIdx.x;
    int nt = gridDim.x * blockDim.x;
    for (int i = tid; i < KB * HH; i += nt) {
        int h = i & 1023;
        d_h[i] = h0[h];
        d_c[i] = c0[h];
    }
    for (int i = tid; i < KB * 2048; i += nt) {
        int p = i & 2047;
        d_xy[i] = (p < 1024) ? emb[(size_t)START_ * EE + p] : 0.f;
    }
    for (int i = tid; i < KB * (TT + 1); i += nt)
        d_tok[0][i] = (i % (TT + 1) == 0) ? START_ : PAD_;
    if (tid < KB) { d_scores[tid] = (tid == 0) ? 0.f : NEGF; d_fin[tid] = 0; }
}

__global__ void k_prep(const float* __restrict__ enc, const float* __restrict__ W,
                       int ldw, int mode) {
    __shared__ float smW[16][129];
    __shared__ float smE[16][129];
    int j0 = blockIdx.x * 16, s0 = blockIdx.y * 16;
    int tid = threadIdx.x;
    int jj = tid & 15, ssn = tid >> 4;
    float acc = 0.f;
    for (int vc = 0; vc < 2 * EE; vc += 128) {
        for (int l = tid; l < 16 * 128; l += 256) {
            int r = l >> 7, cc = l & 127;
            smW[r][cc] = W[(size_t)(j0 + r) * ldw + vc + cc];
            smE[r][cc] = enc[(size_t)(s0 + r) * (2 * EE) + vc + cc];
        }
        __syncthreads();
        #pragma unroll
        for (int x = 0; x < 128; x++) acc += smW[jj][x] * smE[ssn][x];
        __syncthreads();
    }
    int j = j0 + jj, s = s0 + ssn;
    if (mode == 0) d_keys[s * HH + j] = acc;
    else           d_Pt[j * SS + s] = acc;
}

// ---- gates GEMV v2: split-K x4, smem y, depth-2 ALTERNATING prefetch ----
__global__ void __launch_bounds__(256, 1) k_gates(
        const float* __restrict__ W_ih, const float* __restrict__ W_hh) {
    __shared__ __align__(16) float s_y[KB * 768];   // 30KB
    int tid = threadIdx.x, wid = tid >> 5, lane = tid & 31;
    int rb = blockIdx.x >> 2;
    int ks = blockIdx.x & 3;

    for (int i = tid; i < KB * 192; i += 256) {
        int k = i / 192, c4 = i - (i / 192) * 192;
        int gc4 = ks * 192 + c4;
        float4 v = (gc4 < 512) ? ((const float4*)(d_xy + k * 2048))[gc4]
                               : ((const float4*)(d_h + k * 1024))[gc4 - 512];
        ((float4*)s_y)[k * 192 + c4] = v;
    }
    __syncthreads();

    int r0 = rb * 16 + wid * 2;
    const float4* ih0 = (const float4*)(W_ih + (size_t)(r0 + 0) * 2048);
    const float4* ih1 = (const float4*)(W_ih + (size_t)(r0 + 1) * 2048);
    const float4* hh0 = (const float4*)(W_hh + (size_t)(r0 + 0) * 1024);
    const float4* hh1 = (const float4*)(W_hh + (size_t)(r0 + 1) * 1024);

    float4 wbuf[2][2];
    #define LDW(it, buf) { \
        int g_ = ks * 192 + (it) * 32 + lane; \
        if (g_ < 512) { wbuf[buf][0] = ih0[g_]; wbuf[buf][1] = ih1[g_]; } \
        else          { wbuf[buf][0] = hh0[g_ - 512]; wbuf[buf][1] = hh1[g_ - 512]; } }

    LDW(0, 0);
    float acc[2][KB];
    #pragma unroll
    for (int r = 0; r < 2; r++)
        #pragma unroll
        for (int k = 0; k < KB; k++) acc[r][k] = 0.f;

    #pragma unroll
    for (int it = 0; it < 6; it++) {
        if (it + 1 < 6) { LDW(it + 1, (it + 1) & 1); }   // prefetch into OTHER buffer
        float4 a0 = wbuf[it & 1][0], a1 = wbuf[it & 1][1];
        const float4* ys = (const float4*)s_y;
        #pragma unroll
        for (int k = 0; k < KB; k++) {
            float4 yv = ys[k * 192 + it * 32 + lane];
            acc[0][k] += dot4(a0, yv);
            acc[1][k] += dot4(a1, yv);
        }
    }
    #undef LDW
    #pragma unroll
    for (int r = 0; r < 2; r++)
        #pragma unroll
        for (int k = 0; k < KB; k++) {
            float v = acc[r][k];
            for (int o = 16; o; o >>= 1) v += __shfl_down_sync(0xffffffffu, v, o);
            if (lane == 0) d_gp[ks][k * 4096 + r0 + r] = v;
        }
}

// ---- LSTM cell (combine 4 partials + bias) + attention + softmax ----
__global__ void __launch_bounds__(1024) k_attn(const int* __restrict__ src_len,
        const float* __restrict__ b_ih, const float* __restrict__ b_hh) {
    int k = blockIdx.x;
    int tid = threadIdx.x;
    __shared__ float s_h[1024];
    __shared__ float s_e[128];
    __shared__ float s_m, s_t;
    int j = tid;
    float gi = d_gp[0][k * 4096 + j] + d_gp[1][k * 4096 + j]
             + d_gp[2][k * 4096 + j] + d_gp[3][k * 4096 + j]
             + b_ih[j] + b_hh[j];
    int j2 = 1024 + j;
    float gf = d_gp[0][k * 4096 + j2] + d_gp[1][k * 4096 + j2]
             + d_gp[2][k * 4096 + j2] + d_gp[3][k * 4096 + j2]
             + b_ih[j2] + b_hh[j2];
    int j3 = 2048 + j;
    float gg = d_gp[0][k * 4096 + j3] + d_gp[1][k * 4096 + j3]
             + d_gp[2][k * 4096 + j3] + d_gp[3][k * 4096 + j3]
             + b_ih[j3] + b_hh[j3];
    int j4 = 3072 + j;
    float go = d_gp[0][k * 4096 + j4] + d_gp[1][k * 4096 + j4]
             + d_gp[2][k * 4096 + j4] + d_gp[3][k * 4096 + j4]
             + b_ih[j4] + b_hh[j4];
    float cp = d_c[k * 1024 + j];
    float cn = sigm(gf) * cp + sigm(gi) * tanhf(gg);
    float hn = sigm(go) * tanhf(cn);
    d_cn[k * 1024 + j] = cn;
    d_hn[k * 1024 + j] = hn;
    s_h[j] = hn;
    __syncthreads();
    int wid = tid >> 5, lane = tid & 31;
    int slen = src_len[0];
    #pragma unroll
    for (int si = 0; si < 4; si++) {
        int s = wid * 4 + si;
        const float4* kr = (const float4*)(d_keys + s * 1024);
        const float4* hh = (const float4*)s_h;
        float a = 0.f;
        #pragma unroll
        for (int it = 0; it < 8; it++)
            a += dot4(kr[it * 32 + lane], hh[it * 32 + lane]);
        for (int o = 16; o; o >>= 1) a += __shfl_down_sync(0xffffffffu, a, o);
        if (lane == 0) s_e[s] = (s >= slen) ? NEGF : a;
    }
    __syncthreads();
    if (wid == 0) {
        float v0 = s_e[lane], v1 = s_e[lane + 32], v2 = s_e[lane + 64], v3 = s_e[lane + 96];
        float m = fmaxf(fmaxf(v0, v1), fmaxf(v2, v3));
        for (int o = 16; o; o >>= 1) m = fmaxf(m, __shfl_xor_sync(0xffffffffu, m, o));
        float t = expf(v0 - m) + expf(v1 - m) + expf(v2 - m) + expf(v3 - m);
        for (int o = 16; o; o >>= 1) t += __shfl_xor_sync(0xffffffffu, t, o);
        if (lane == 0) { s_m = m; s_t = t; }
    }
    __syncthreads();
    if (tid < 128) d_alpha[k * 128 + tid] = expf(s_e[tid] - s_m) / s_t;
}

__global__ void __launch_bounds__(128) k_out(const float* __restrict__ W_comb) {
    int j = blockIdx.x, tid = threadIdx.x;
    float acc[KB];
    #pragma unroll
    for (int k = 0; k < KB; k++) acc[k] = 0.f;
    {
        float p = d_Pt[j * 128 + tid];
        #pragma unroll
        for (int k = 0; k < KB; k++) acc[k] += d_alpha[k * 128 + tid] * p;
    }
    const float4* w4 = (const float4*)(W_comb + (size_t)j * 3072 + 2048);
    #pragma unroll
    for (int it = 0; it < 2; it++) {
        int ix = it * 128 + tid;
        float4 a = w4[ix];
        #pragma unroll
        for (int k = 0; k < KB; k++)
            acc[k] += dot4(a, ((const float4*)(d_hn + k * 1024))[ix]);
    }
    __shared__ float sp[4][KB];
    int wid = tid >> 5, lane = tid & 31;
    #pragma unroll
    for (int k = 0; k < KB; k++) {
        float v = acc[k];
        for (int o = 16; o; o >>= 1) v += __shfl_down_sync(0xffffffffu, v, o);
        if (lane == 0) sp[wid][k] = v;
    }
    __syncthreads();
    if (tid < KB) {
        float v = sp[0][tid] + sp[1][tid] + sp[2][tid] + sp[3][tid];
        d_on[tid * HH + j] = tanhf(v);
    }
}

// ---- logits v2: 32 rows/block, depth-2 alternating prefetch, fused stats/top-10 ----
__global__ void __launch_bounds__(256, 1) k_logits(const float* __restrict__ Wv) {
    __shared__ float s_on[KB * 1024];
    __shared__ float s_lg[KB][32];
    int tid = threadIdx.x, wid = tid >> 5, lane = tid & 31;
    {
        const float4* src = (const float4*)d_on;
        float4* dst = (float4*)s_on;
        for (int i = tid; i < KB * 256; i += 256) dst[i] = src[i];
    }
    __syncthreads();
    int base = blockIdx.x * 32;
    int r0 = base + wid * 4;

    const float4* w0 = (const float4*)(Wv + (size_t)(r0 + 0) * 1024);
    const float4* w1 = (const float4*)(Wv + (size_t)(r0 + 1) * 1024);
    const float4* w2 = (const float4*)(Wv + (size_t)(r0 + 2) * 1024);
    const float4* w3 = (const float4*)(Wv + (size_t)(r0 + 3) * 1024);

    float4 wb[2][4];
    #define LDWV(it, buf) { int g_ = (it) * 32 + lane; \
        wb[buf][0] = w0[g_]; wb[buf][1] = w1[g_]; \
        wb[buf][2] = w2[g_]; wb[buf][3] = w3[g_]; }

    LDWV(0, 0);
    float acc[4][KB];
    #pragma unroll
    for (int r = 0; r < 4; r++)
        #pragma unroll
        for (int k = 0; k < KB; k++) acc[r][k] = 0.f;

    #pragma unroll
    for (int it = 0; it < 8; it++) {
        if (it + 1 < 8) { LDWV(it + 1, (it + 1) & 1); }
        float4 a0 = wb[it & 1][0], a1 = wb[it & 1][1];
        float4 a2 = wb[it & 1][2], a3 = wb[it & 1][3];
        const float4* ys = (const float4*)s_on;
        #pragma unroll
        for (int k = 0; k < KB; k++) {
            float4 yv = ys[k * 256 + it * 32 + lane];
            acc[0][k] += dot4(a0, yv); acc[1][k] += dot4(a1, yv);
            acc[2][k] += dot4(a2, yv); acc[3][k] += dot4(a3, yv);
        }
    }
    #undef LDWV
    #pragma unroll
    for (int r = 0; r < 4; r++)
        #pragma unroll
        for (int k = 0; k < KB; k++) {
            float v = acc[r][k];
            for (int o = 16; o; o >>= 1) v += __shfl_down_sync(0xffffffffu, v, o);
            if (lane == 0) s_lg[k][wid * 4 + r] = v;
        }
    __syncthreads();

    for (int k = wid; k < KB; k += 8) {
        float v = s_lg[k][lane];
        int idx = k * VV + base + lane;
        float m = v;
        for (int o = 16; o; o >>= 1) m = fmaxf(m, __shfl_xor_sync(0xffffffffu, m, o));
        float ssum = expf(v - m);
        for (int o = 16; o; o >>= 1) ssum += __shfl_xor_sync(0xffffffffu, ssum, o);
        if (lane == 0) {
            d_pmax[blockIdx.x * KB + k] = m;
            d_psum[blockIdx.x * KB + k] = ssum;
        }
        float lv[10]; int li[10];
        lv[0] = v; li[0] = idx;
        #pragma unroll
        for (int p = 1; p < 10; p++) { lv[p] = -FLT_MAX; li[p] = 0x7fffffff; }
        merge32(lv, li, lane,
                &d_ptv[(blockIdx.x * KB + k) * 10], &d_pti[(blockIdx.x * KB + k) * 10]);
    }
}

// ---- per-beam reduction of 1000 partial lists + exact max/lse ----
__global__ void __launch_bounds__(256) k_reduce() {
    int k = blockIdx.x;
    int tid = threadIdx.x, wid = tid >> 5, lane = tid & 31;
    __shared__ float s_red[8];
    __shared__ float s_m;
    __shared__ float s_wv[8 * 10];
    __shared__ int s_wi[8 * 10];

    float m = -FLT_MAX;
    for (int b = tid; b < NLOG_BLK; b += 256) m = fmaxf(m, d_pmax[b * KB + k]);
    for (int o = 16; o; o >>= 1) m = fmaxf(m, __shfl_xor_sync(0xffffffffu, m, o));
    if (lane == 0) s_red[wid] = m;
    __syncthreads();
    if (tid == 0) {
        float v = -FLT_MAX;
        #pragma unroll
        for (int i = 0; i < 8; i++) v = fmaxf(v, s_red[i]);
        s_m = v;
    }
    __syncthreads();
    float mm = s_m;
    float s = 0.f;
    for (int b = tid; b < NLOG_BLK; b += 256)
        s += d_psum[b * KB + k] * expf(d_pmax[b * KB + k] - mm);
    for (int o = 16; o; o >>= 1) s += __shfl_xor_sync(0xffffffffu, s, o);
    if (lane == 0) s_red[wid] = s;
    __syncthreads();
    if (tid == 0) {
        float v = 0.f;
        #pragma unroll
        for (int i = 0; i < 8; i++) v += s_red[i];
        d_mx[k] = mm;
        d_lse[k] = logf(v);
    }

    float lv[10]; int li[10];
    #pragma unroll
    for (int p = 0; p < 10; p++) { lv[p] = -FLT_MAX; li[p] = 0x7fffffff; }
    for (int e = tid; e < NLOG_BLK * 10; e += 256) {
        int blk = e / 10, r = e - blk * 10;
        ins10(d_ptv[(blk * KB + k) * 10 + r], d_pti[(blk * KB + k) * 10 + r], lv, li);
    }
    merge32(lv, li, lane, &s_wv[wid * 10], &s_wi[wid * 10]);
    __syncthreads();
    if (wid == 0) {
        float lv2[10]; int li2[10];
        #pragma unroll
        for (int p = 0; p < 10; p++) { lv2[p] = -FLT_MAX; li2[p] = 0x7fffffff; }
        if (lane < 8)
            #pragma unroll
            for (int p = 0; p < 10; p++) { lv2[p] = s_wv[lane * 10 + p]; li2[p] = s_wi[lane * 10 + p]; }
        merge32(lv2, li2, lane, &d_btv[k * 10], &d_bti[k * 10]);
    }
}

// ---- merge 100 candidates, token update, fused gather ----
__global__ void __launch_bounds__(1024) k_merge(int t, int cur,
                                                const float* __restrict__ emb) {
    int tid = threadIdx.x;
    int wid = tid >> 5, lane = tid & 31;
    __shared__ float s_mx[KB], s_ls[KB], s_sc[KB];
    __shared__ int s_fin[KB];
    __shared__ float s_wv[320];
    __shared__ int s_wi[320];
    __shared__ float s_tv[KB];
    __shared__ int s_ti[KB];
    __shared__ int s_row[KB], s_col[KB];
    if (tid < KB) {
        s_sc[tid] = d_scores[tid]; s_fin[tid] = d_fin[tid];
        s_mx[tid] = d_mx[tid]; s_ls[tid] = d_lse[tid];
    }
    __syncthreads();

    float lv[10]; int li[10];
    #pragma unroll
    for (int p = 0; p < 10; p++) { lv[p] = -FLT_MAX; li[p] = 0x7fffffff; }
    if (tid < KB * 10) {
        int k = tid / 10;
        if (!s_fin[k])
            ins10(s_sc[k] + d_btv[tid] - s_mx[k] - s_ls[k], d_bti[tid], lv, li);
    }
    if (tid >= 512 && tid - 512 < KB && s_fin[tid - 512])
        ins10(s_sc[tid - 512], (tid - 512) * VV + PAD_, lv, li);

    merge32(lv, li, lane, &s_wv[wid * 10], &s_wi[wid * 10]);
    __syncthreads();
    if (wid == 0) {
        int hd = 0;
        for (int r = 0; r < 10; r++) {
            float cv = (hd < 10) ? s_wv[lane * 10 + hd] : -FLT_MAX;
            int ci = (hd < 10) ? s_wi[lane * 10 + hd] : 0x7fffffff;
            float bv = cv; int bi = ci; int bl = lane;
            for (int o = 16; o; o >>= 1) {
                float ov = __shfl_down_sync(0xffffffffu, bv, o);
                int oi = __shfl_down_sync(0xffffffffu, bi, o);
                int ol = __shfl_down_sync(0xffffffffu, bl, o);
                if (ov > bv || (ov == bv && oi < bi)) { bv = ov; bi = oi; bl = ol; }
            }
            bv = __shfl_sync(0xffffffffu, bv, 0);
            bi = __shfl_sync(0xffffffffu, bi, 0);
            bl = __shfl_sync(0xffffffffu, bl, 0);
            if (lane == bl) hd++;
            if (lane == 0) { s_tv[r] = bv; s_ti[r] = bi; }
        }
    }
    __syncthreads();

    if (tid < KB) {
        int ix = s_ti[tid];
        int r = ix / VV;
        int col = ix - r * VV;
        s_row[tid] = r; s_col[tid] = col;
        d_scores[tid] = s_tv[tid];
        d_fin[tid] = (s_fin[r] || (col == EOS_)) ? 1 : 0;
    }
    __syncthreads();

    int nxt = cur ^ 1;
    for (int i = tid; i < KB * (TT + 1); i += 1024) {
        int b = i / (TT + 1), p = i - b * (TT + 1);
        int val = (p == t + 1) ? s_col[b] : d_tok[cur][s_row[b] * (TT + 1) + p];
        d_tok[nxt][i] = val;
    }
    for (int i = tid; i < KB * 1024; i += 1024) {
        int b = i >> 10, h2 = i & 1023;
        int r = s_row[b];
        d_h[i] = d_hn[r * 1024 + h2];
        d_c[i] = d_cn[r * 1024 + h2];
        d_xy[b * 2048 + 1024 + h2] = d_on[r * 1024 + h2];
        d_xy[b * 2048 + h2] = emb[(size_t)s_col[b] * EE + h2];
    }
}

__global__ void k_final(float* __restrict__ out, int n) {
    int tid = blockIdx.x * blockDim.x + threadIdx.x;
    int ntok = KB * (TT + 1);
    int fin = TT & 1;
    for (int i = tid; i < n; i += gridDim.x * blockDim.x) {
        if (i < ntok) out[i] = (float)d_tok[fin][i];
        else if (i < ntok + KB) out[i] = d_scores[i - ntok];
        else out[i] = 0.f;
    }
}

extern "C" void kernel_launch(void* const* d_in, const int* in_sizes, int n_in,
                              void* d_out, int out_size) {
    const float* enc  = (const float*)d_in[0];
    const float* h0   = (const float*)d_in[1];
    const float* c0   = (const float*)d_in[2];
    const float* emb  = (const float*)d_in[3];
    const float* W_ih = (const float*)d_in[4];
    const float* b_ih = (const float*)d_in[5];
    const float* W_hh = (const float*)d_in[6];
    const float* b_hh = (const float*)d_in[7];
    const float* W_at = (const float*)d_in[8];
    const float* W_cb = (const float*)d_in[9];
    const float* W_vb = (const float*)d_in[10];
    const int* srcl   = (const int*)d_in[11];

    k_init<<<48, 256>>>(h0, c0, emb);
    k_prep<<<dim3(HH / 16, SS / 16), 256>>>(enc, W_at, 2 * EE, 0);
    k_prep<<<dim3(HH / 16, SS / 16), 256>>>(enc, W_cb, 2 * EE + HH, 1);

    for (int t = 0; t < TT; t++) {
        int cur = t & 1;
        k_gates<<<1024, 256>>>(W_ih, W_hh);
        k_attn<<<KB, 1024>>>(srcl, b_ih, b_hh);
        k_out<<<HH, 128>>>(W_cb);
        k_logits<<<NLOG_BLK, 256>>>(W_vb);
        k_reduce<<<KB, 256>>>();
        k_merge<<<1, 1024>>>(t, cur, emb);
    }
    k_final<<<1, 256>>>((float*)d_out, out_size);
}